// round 1
// baseline (speedup 1.0000x reference)
#include <cuda_runtime.h>
#include <math.h>

// Problem constants
#define BATCH 8
#define SEQ   2048
#define DIM   768

// Scratch (allocation-free rule: __device__ globals)
// g_qkv: [3][BATCH*SEQ*DIM]  (q, k, v contiguous slabs)
// g_s:   [BATCH][SEQ][SEQ]   attention scores / probs
__device__ float g_qkv[3ULL * BATCH * SEQ * DIM];
__device__ float g_s[(size_t)BATCH * SEQ * SEQ];

// ---------------------------------------------------------------------------
// Tiled fp32 GEMM: C[M,N] = alpha * A[M,K] @ op(B)
//   TRANSB=false: B is [K,N] row-major (NN)
//   TRANSB=true : B is [N,K] row-major (NT, i.e. C = A @ B^T)
// Block tile 128x128x8, 256 threads, 8x8 per-thread micro-tile.
// Requires: M%128==0, N%128==0, K%8==0 (true for all our shapes).
// blockIdx.z batches with the given strides.
// ---------------------------------------------------------------------------
template <bool TRANSB>
__global__ void __launch_bounds__(256)
sgemm_kernel(const float* __restrict__ A,
             const float* __restrict__ B,
             float* __restrict__ C,
             int M, int N, int K,
             long strideA, long strideB, long strideC,
             float alpha)
{
    const int bz = blockIdx.z;
    A += (long)bz * strideA;
    B += (long)bz * strideB;
    C += (long)bz * strideC;

    __shared__ float As[8][128];
    __shared__ float Bs[8][128];

    const int tid = threadIdx.x;
    const int tx  = tid & 15;    // 0..15  (column group)
    const int ty  = tid >> 4;    // 0..15  (row group)

    const int bm = blockIdx.y * 128;
    const int bn = blockIdx.x * 128;

    // Loader indices
    const int a_row = tid >> 1;          // 0..127
    const int a_col = (tid & 1) * 4;     // 0 or 4
    const int b_row = tid >> 5;          // 0..7   (NN only)
    const int b_col = (tid & 31) * 4;    // 0..124 (NN only)

    float acc[8][8];
#pragma unroll
    for (int i = 0; i < 8; i++)
#pragma unroll
        for (int j = 0; j < 8; j++) acc[i][j] = 0.0f;

    for (int k0 = 0; k0 < K; k0 += 8) {
        // Load A tile [128 x 8], store transposed As[k][m]
        float4 av = *reinterpret_cast<const float4*>(
            &A[(long)(bm + a_row) * K + (k0 + a_col)]);
        As[a_col + 0][a_row] = av.x;
        As[a_col + 1][a_row] = av.y;
        As[a_col + 2][a_row] = av.z;
        As[a_col + 3][a_row] = av.w;

        if (TRANSB) {
            // B is [N,K]: tile rows = n (128), cols = k (8). Same pattern as A.
            float4 bv = *reinterpret_cast<const float4*>(
                &B[(long)(bn + a_row) * K + (k0 + a_col)]);
            Bs[a_col + 0][a_row] = bv.x;
            Bs[a_col + 1][a_row] = bv.y;
            Bs[a_col + 2][a_row] = bv.z;
            Bs[a_col + 3][a_row] = bv.w;
        } else {
            // B is [K,N]: tile rows = k (8), cols = n (128).
            float4 bv = *reinterpret_cast<const float4*>(
                &B[(long)(k0 + b_row) * N + (bn + b_col)]);
            *reinterpret_cast<float4*>(&Bs[b_row][b_col]) = bv;
        }
        __syncthreads();

#pragma unroll
        for (int kk = 0; kk < 8; kk++) {
            float ra[8], rb[8];
            *reinterpret_cast<float4*>(&ra[0]) =
                *reinterpret_cast<const float4*>(&As[kk][ty * 4]);
            *reinterpret_cast<float4*>(&ra[4]) =
                *reinterpret_cast<const float4*>(&As[kk][64 + ty * 4]);
            *reinterpret_cast<float4*>(&rb[0]) =
                *reinterpret_cast<const float4*>(&Bs[kk][tx * 4]);
            *reinterpret_cast<float4*>(&rb[4]) =
                *reinterpret_cast<const float4*>(&Bs[kk][64 + tx * 4]);
#pragma unroll
            for (int i = 0; i < 8; i++)
#pragma unroll
                for (int j = 0; j < 8; j++)
                    acc[i][j] += ra[i] * rb[j];
        }
        __syncthreads();
    }

    // Write back (two 64-row halves x two 64-col halves)
#pragma unroll
    for (int ih = 0; ih < 2; ih++) {
#pragma unroll
        for (int i = 0; i < 4; i++) {
            const int ai  = ih * 4 + i;
            const int row = bm + ih * 64 + ty * 4 + i;
            float* cp = &C[(long)row * N + bn];
            float4 w0 = make_float4(acc[ai][0] * alpha, acc[ai][1] * alpha,
                                    acc[ai][2] * alpha, acc[ai][3] * alpha);
            float4 w1 = make_float4(acc[ai][4] * alpha, acc[ai][5] * alpha,
                                    acc[ai][6] * alpha, acc[ai][7] * alpha);
            *reinterpret_cast<float4*>(cp + tx * 4)      = w0;
            *reinterpret_cast<float4*>(cp + 64 + tx * 4) = w1;
        }
    }
}

// ---------------------------------------------------------------------------
// Row softmax over g_s: one block per row (BATCH*SEQ rows, SEQ=2048 cols).
// 256 threads, 8 values per thread kept in registers (single gmem read+write).
// ---------------------------------------------------------------------------
__global__ void __launch_bounds__(256)
softmax_kernel(float* __restrict__ S)
{
    const long row = blockIdx.x;
    float* p = S + row * (long)SEQ;
    const int t = threadIdx.x;

    __shared__ float red[8];

    float v[8];
    float m = -1e30f;
#pragma unroll
    for (int i = 0; i < 8; i++) {
        v[i] = p[t + i * 256];
        m = fmaxf(m, v[i]);
    }

    // block max
#pragma unroll
    for (int o = 16; o > 0; o >>= 1)
        m = fmaxf(m, __shfl_xor_sync(0xffffffff, m, o));
    const int warp = t >> 5, lane = t & 31;
    if (lane == 0) red[warp] = m;
    __syncthreads();
    m = red[0];
#pragma unroll
    for (int w = 1; w < 8; w++) m = fmaxf(m, red[w]);
    __syncthreads();

    float s = 0.0f;
#pragma unroll
    for (int i = 0; i < 8; i++) {
        v[i] = __expf(v[i] - m);
        s += v[i];
    }

    // block sum
#pragma unroll
    for (int o = 16; o > 0; o >>= 1)
        s += __shfl_xor_sync(0xffffffff, s, o);
    if (lane == 0) red[warp] = s;
    __syncthreads();
    s = red[0];
#pragma unroll
    for (int w = 1; w < 8; w++) s += red[w];

    const float inv = 1.0f / s;
#pragma unroll
    for (int i = 0; i < 8; i++)
        p[t + i * 256] = v[i] * inv;
}

// ---------------------------------------------------------------------------
// Launch
// ---------------------------------------------------------------------------
extern "C" void kernel_launch(void* const* d_in, const int* in_sizes, int n_in,
                              void* d_out, int out_size)
{
    const float* x   = (const float*)d_in[0];   // [B, S, D]
    const float* QKV = (const float*)d_in[1];   // [3, D, D]
    float* out = (float*)d_out;                 // [B, S, D]

    float* qkv = nullptr;
    float* s   = nullptr;
    cudaGetSymbolAddress((void**)&qkv, g_qkv);
    cudaGetSymbolAddress((void**)&s,   g_s);

    const long BSD = (long)BATCH * SEQ * DIM;     // 12,582,912
    float* q = qkv;
    float* k = qkv + BSD;
    float* v = qkv + 2 * BSD;

    const float scale = 1.0f / sqrtf((float)DIM);

    // 1) QKV projection: [16384,768] @ [768,768] for each of 3 weights (grid.z)
    {
        dim3 grid(DIM / 128, (BATCH * SEQ) / 128, 3);
        sgemm_kernel<false><<<grid, 256>>>(
            x, QKV, qkv,
            BATCH * SEQ, DIM, DIM,
            /*strideA=*/0, /*strideB=*/(long)DIM * DIM, /*strideC=*/BSD,
            1.0f);
    }

    // 2) scores = scale * Q @ K^T, per batch (grid.z)
    {
        dim3 grid(SEQ / 128, SEQ / 128, BATCH);
        sgemm_kernel<true><<<grid, 256>>>(
            q, k, s,
            SEQ, SEQ, DIM,
            /*strideA=*/(long)SEQ * DIM, /*strideB=*/(long)SEQ * DIM,
            /*strideC=*/(long)SEQ * SEQ,
            scale);
    }

    // 3) softmax rows
    softmax_kernel<<<BATCH * SEQ, 256>>>(s);

    // 4) out = P @ V, per batch (grid.z)
    {
        dim3 grid(DIM / 128, SEQ / 128, BATCH);
        sgemm_kernel<false><<<grid, 256>>>(
            s, v, out,
            SEQ, DIM, SEQ,
            /*strideA=*/(long)SEQ * SEQ, /*strideB=*/(long)SEQ * DIM,
            /*strideC=*/(long)SEQ * DIM,
            1.0f);
    }
}

// round 3
// speedup vs baseline: 2.2658x; 2.2658x over previous
#include <cuda_runtime.h>
#include <cuda_bf16.h>
#include <math.h>
#include <stdint.h>

// ---------------------------------------------------------------------------
// Problem constants
// ---------------------------------------------------------------------------
#define BATCH 8
#define SEQ   2048
#define DIM   768

// ---------------------------------------------------------------------------
// Scratch (__device__ globals; no allocation allowed)
// ---------------------------------------------------------------------------
__device__ __nv_bfloat16 g_xh[(size_t)BATCH * SEQ * DIM];
__device__ __nv_bfloat16 g_xl[(size_t)BATCH * SEQ * DIM];
__device__ __nv_bfloat16 g_wth[3ULL * DIM * DIM];   // W^T per slice, [z][n][k]
__device__ __nv_bfloat16 g_wtl[3ULL * DIM * DIM];
__device__ __nv_bfloat16 g_qh[(size_t)BATCH * SEQ * DIM];
__device__ __nv_bfloat16 g_ql[(size_t)BATCH * SEQ * DIM];
__device__ __nv_bfloat16 g_kh[(size_t)BATCH * SEQ * DIM];
__device__ __nv_bfloat16 g_kl[(size_t)BATCH * SEQ * DIM];
__device__ __nv_bfloat16 g_vth[(size_t)BATCH * DIM * SEQ];  // V^T: [b][d][s]
__device__ __nv_bfloat16 g_vtl[(size_t)BATCH * DIM * SEQ];
__device__ float         g_s[(size_t)BATCH * SEQ * SEQ];    // fp32 logits
__device__ __nv_bfloat16 g_ph[(size_t)BATCH * SEQ * SEQ];   // probs hi/lo
__device__ __nv_bfloat16 g_pl[(size_t)BATCH * SEQ * SEQ];

// ---------------------------------------------------------------------------
// Helpers
// ---------------------------------------------------------------------------
__device__ __forceinline__ uint32_t smem_u32(const void* p) {
    uint32_t a;
    asm("{ .reg .u64 t; cvta.to.shared.u64 t, %1; cvt.u32.u64 %0, t; }"
        : "=r"(a) : "l"(p));
    return a;
}

__device__ __forceinline__ __nv_bfloat16 bf_hi(float f) {
    return __float2bfloat16_rn(f);
}
__device__ __forceinline__ __nv_bfloat16 bf_lo(float f, __nv_bfloat16 h) {
    return __float2bfloat16_rn(f - __bfloat162float(h));
}

#define LDSM4(r, addr) \
    asm volatile("ldmatrix.sync.aligned.m8n8.x4.shared.b16 {%0,%1,%2,%3}, [%4];" \
        : "=r"((r)[0]), "=r"((r)[1]), "=r"((r)[2]), "=r"((r)[3]) : "r"(addr))

#define MMA_BF16(d, a, b) \
    asm volatile("mma.sync.aligned.m16n8k16.row.col.f32.bf16.bf16.f32 " \
        "{%0,%1,%2,%3}, {%4,%5,%6,%7}, {%8,%9}, {%0,%1,%2,%3};" \
        : "+f"((d)[0]), "+f"((d)[1]), "+f"((d)[2]), "+f"((d)[3]) \
        : "r"((a)[0]), "r"((a)[1]), "r"((a)[2]), "r"((a)[3]), \
          "r"((b)[0]), "r"((b)[1]))

#define CP_ASYNC16(dst, src) \
    asm volatile("cp.async.cg.shared.global [%0], [%1], 16;" \
        :: "r"(dst), "l"(src))
#define CP_COMMIT()  asm volatile("cp.async.commit_group;")
#define CP_WAIT1()   asm volatile("cp.async.wait_group 1;")
#define CP_WAIT0()   asm volatile("cp.async.wait_group 0;")

// ---------------------------------------------------------------------------
// GEMM tiling: BM=128, BN=128, BK=32 bf16; 8 warps (2 m x 4 n), warp 64x32.
// SMEM per stage: 4 operand tiles (A_hi, A_lo, B_hi, B_lo), each 128 rows x
// 32 bf16, padded row stride 40 elems (80B; conflict-free for ldmatrix).
// ---------------------------------------------------------------------------
#define TSTRIDE 40
#define TILE_B  (128 * TSTRIDE * 2)      // 10240 bytes per operand tile
#define STAGE_B (4 * TILE_B)             // 40960
#define SMEM_TOTAL (2 * STAGE_B)         // 81920

// MODE 0: QKV proj (K=768;  z = weight slice; -> q/k hi/lo, V^T hi/lo)
// MODE 1: Q @ K^T  (K=768;  z = batch; -> fp32 logits * alpha)
// MODE 2: P @ V^T  (K=2048; z = batch; -> fp32 d_out)
template <int MODE>
__global__ void __launch_bounds__(256)
gemm_mma(const __nv_bfloat16* __restrict__ Ah, const __nv_bfloat16* __restrict__ Al,
         const __nv_bfloat16* __restrict__ Bh, const __nv_bfloat16* __restrict__ Bl,
         float* __restrict__ outF,
         __nv_bfloat16* __restrict__ o0h, __nv_bfloat16* __restrict__ o0l,
         __nv_bfloat16* __restrict__ o1h, __nv_bfloat16* __restrict__ o1l,
         __nv_bfloat16* __restrict__ o2h, __nv_bfloat16* __restrict__ o2l,
         float alpha)
{
    constexpr int  K  = (MODE == 2) ? 2048 : 768;
    constexpr long sA = (MODE == 0) ? 0L
                       : (MODE == 1) ? (long)SEQ * DIM : (long)SEQ * SEQ;
    constexpr long sB = (MODE == 0) ? (long)DIM * DIM
                       : (MODE == 1) ? (long)SEQ * DIM : (long)DIM * SEQ;
    constexpr int NC  = K / 32;

    extern __shared__ char smem[];
    const uint32_t sbase = smem_u32(smem);

    const int tid  = threadIdx.x;
    const int wid  = tid >> 5;
    const int lane = tid & 31;
    const int wm   = wid & 1;      // 0..1
    const int wn   = wid >> 1;     // 0..3
    const int z    = blockIdx.z;
    const int bm   = blockIdx.y * 128;
    const int bn   = blockIdx.x * 128;

    const __nv_bfloat16* gA[2] = { Ah + (long)z * sA + (long)bm * K,
                                   Al + (long)z * sA + (long)bm * K };
    const __nv_bfloat16* gB[2] = { Bh + (long)z * sB + (long)bn * K,
                                   Bl + (long)z * sB + (long)bn * K };

    // Per-thread gmem load coords: 512 16B-chunks per tile; 2 per thread.
    const int l_row0 = (tid + 0)   >> 2, l_c0 = (tid + 0)   & 3;
    const int l_row1 = (tid + 256) >> 2, l_c1 = (tid + 256) & 3;

    auto load_stage = [&](int buf, int k0) {
        const uint32_t soff = sbase + buf * STAGE_B;
#pragma unroll
        for (int op = 0; op < 4; op++) {
            const __nv_bfloat16* g = (op < 2) ? gA[op] : gB[op - 2];
            CP_ASYNC16(soff + op * TILE_B + l_row0 * (TSTRIDE * 2) + l_c0 * 16,
                       g + (long)l_row0 * K + k0 + l_c0 * 8);
            CP_ASYNC16(soff + op * TILE_B + l_row1 * (TSTRIDE * 2) + l_c1 * 16,
                       g + (long)l_row1 * K + k0 + l_c1 * 8);
        }
        CP_COMMIT();
    };

    // ldmatrix per-thread addressing
    const int rA = lane & 15;                          // A row within 16
    const int cA = (lane >> 4) << 3;                   // 0 or 8 (k)
    const int rB = (lane & 7) | ((lane >> 4) << 3);    // B row within 16 (n)
    const int cB = ((lane >> 3) & 1) << 3;             // 0 or 8 (k)

    float acc[4][4][4];
#pragma unroll
    for (int mf = 0; mf < 4; mf++)
#pragma unroll
        for (int nf = 0; nf < 4; nf++)
#pragma unroll
            for (int q = 0; q < 4; q++) acc[mf][nf][q] = 0.0f;

    load_stage(0, 0);

    for (int c = 0; c < NC; c++) {
        if (c + 1 < NC) { load_stage((c + 1) & 1, (c + 1) * 32); CP_WAIT1(); }
        else            { CP_WAIT0(); }
        __syncthreads();

        const uint32_t soff = sbase + (c & 1) * STAGE_B;
        const uint32_t aH = soff + 0 * TILE_B;
        const uint32_t aL = soff + 1 * TILE_B;
        const uint32_t bH = soff + 2 * TILE_B;
        const uint32_t bL = soff + 3 * TILE_B;

#pragma unroll
        for (int ks = 0; ks < 2; ks++) {
            const int kb = ks * 32;  // bytes offset: 16 elems * 2B
            uint32_t ah[4][4], al[4][4], bh[4][2], bl[4][2];
#pragma unroll
            for (int mf = 0; mf < 4; mf++) {
                const uint32_t ro =
                    (uint32_t)((wm * 64 + mf * 16 + rA) * (TSTRIDE * 2) + cA * 2 + kb);
                LDSM4(ah[mf], aH + ro);
                LDSM4(al[mf], aL + ro);
            }
#pragma unroll
            for (int nf2 = 0; nf2 < 2; nf2++) {
                const uint32_t ro =
                    (uint32_t)((wn * 32 + nf2 * 16 + rB) * (TSTRIDE * 2) + cB * 2 + kb);
                uint32_t th[4], tl[4];
                LDSM4(th, bH + ro);
                LDSM4(tl, bL + ro);
                bh[nf2 * 2][0] = th[0]; bh[nf2 * 2][1] = th[1];
                bh[nf2 * 2 + 1][0] = th[2]; bh[nf2 * 2 + 1][1] = th[3];
                bl[nf2 * 2][0] = tl[0]; bl[nf2 * 2][1] = tl[1];
                bl[nf2 * 2 + 1][0] = tl[2]; bl[nf2 * 2 + 1][1] = tl[3];
            }
#pragma unroll
            for (int mf = 0; mf < 4; mf++)
#pragma unroll
                for (int nf = 0; nf < 4; nf++) {
                    MMA_BF16(acc[mf][nf], ah[mf], bh[nf]);
                    MMA_BF16(acc[mf][nf], ah[mf], bl[nf]);
                    MMA_BF16(acc[mf][nf], al[mf], bh[nf]);
                }
        }
        __syncthreads();
    }

    // -----------------------------------------------------------------------
    // Epilogue: thread owns (r0, n0..n0+1) and (r0+8, n0..n0+1) per frag.
    // -----------------------------------------------------------------------
    const int gq = lane >> 2;
    const int i2 = (lane & 3) * 2;

#pragma unroll
    for (int mf = 0; mf < 4; mf++) {
#pragma unroll
        for (int nf = 0; nf < 4; nf++) {
            const int n0 = bn + wn * 32 + nf * 8 + i2;
#pragma unroll
            for (int h = 0; h < 2; h++) {
                const int mg = bm + wm * 64 + mf * 16 + gq + h * 8;
                const float f0 = acc[mf][nf][h * 2 + 0];
                const float f1 = acc[mf][nf][h * 2 + 1];

                if (MODE == 0) {
                    if (z < 2) {
                        __nv_bfloat16* dh = (z == 0) ? o0h : o1h;
                        __nv_bfloat16* dl = (z == 0) ? o0l : o1l;
                        __nv_bfloat16 h0 = bf_hi(f0), h1 = bf_hi(f1);
                        __nv_bfloat16 l0 = bf_lo(f0, h0), l1 = bf_lo(f1, h1);
                        const long addr = (long)mg * DIM + n0;
                        __nv_bfloat162 hv; hv.x = h0; hv.y = h1;
                        __nv_bfloat162 lv; lv.x = l0; lv.y = l1;
                        *reinterpret_cast<__nv_bfloat162*>(dh + addr) = hv;
                        *reinterpret_cast<__nv_bfloat162*>(dl + addr) = lv;
                    } else {
                        // V: write transposed V^T[b][d][s]
                        const int b = mg >> 11;
                        const int s = mg & 2047;
                        __nv_bfloat16 h0 = bf_hi(f0), h1 = bf_hi(f1);
                        const long a0 = ((long)b * DIM + n0) * SEQ + s;
                        const long a1 = ((long)b * DIM + n0 + 1) * SEQ + s;
                        o2h[a0] = h0; o2l[a0] = bf_lo(f0, h0);
                        o2h[a1] = h1; o2l[a1] = bf_lo(f1, h1);
                    }
                } else if (MODE == 1) {
                    float* dst = outF + (long)z * SEQ * SEQ + (long)mg * SEQ + n0;
                    float2 v = make_float2(f0 * alpha, f1 * alpha);
                    *reinterpret_cast<float2*>(dst) = v;
                } else {
                    float* dst = outF + (long)z * SEQ * DIM + (long)mg * DIM + n0;
                    float2 v = make_float2(f0, f1);
                    *reinterpret_cast<float2*>(dst) = v;
                }
            }
        }
    }
}

// ---------------------------------------------------------------------------
// Conversion kernels
// ---------------------------------------------------------------------------
__global__ void __launch_bounds__(256)
conv_x_kernel(const float* __restrict__ x,
              __nv_bfloat16* __restrict__ xh, __nv_bfloat16* __restrict__ xl)
{
    const long i = ((long)blockIdx.x * 256 + threadIdx.x) * 4;
    float4 v = *reinterpret_cast<const float4*>(x + i);
    __nv_bfloat16 h[4], l[4];
    h[0] = bf_hi(v.x); l[0] = bf_lo(v.x, h[0]);
    h[1] = bf_hi(v.y); l[1] = bf_lo(v.y, h[1]);
    h[2] = bf_hi(v.z); l[2] = bf_lo(v.z, h[2]);
    h[3] = bf_hi(v.w); l[3] = bf_lo(v.w, h[3]);
    *reinterpret_cast<uint2*>(xh + i) = *reinterpret_cast<uint2*>(h);
    *reinterpret_cast<uint2*>(xl + i) = *reinterpret_cast<uint2*>(l);
}

// Transpose + split QKV weights: W[z][k][n] -> Wt[z][n][k]
__global__ void __launch_bounds__(256)
conv_w_kernel(const float* __restrict__ W,
              __nv_bfloat16* __restrict__ wth, __nv_bfloat16* __restrict__ wtl)
{
    __shared__ float tile[32][33];
    const int z  = blockIdx.z;
    const int bx = blockIdx.x * 32;   // n
    const int by = blockIdx.y * 32;   // k
    const int tx = threadIdx.x & 31;
    const int ty = threadIdx.x >> 5;  // 0..7
    const float* Wz = W + (long)z * DIM * DIM;
#pragma unroll
    for (int i = 0; i < 32; i += 8)
        tile[ty + i][tx] = Wz[(long)(by + ty + i) * DIM + (bx + tx)];
    __syncthreads();
    __nv_bfloat16* th = wth + (long)z * DIM * DIM;
    __nv_bfloat16* tl = wtl + (long)z * DIM * DIM;
#pragma unroll
    for (int i = 0; i < 32; i += 8) {
        float f = tile[tx][ty + i];
        __nv_bfloat16 h = bf_hi(f);
        const long addr = (long)(bx + ty + i) * DIM + (by + tx);
        th[addr] = h;
        tl[addr] = bf_lo(f, h);
    }
}

// ---------------------------------------------------------------------------
// Softmax: fp32 logits row -> bf16 hi/lo probs
// ---------------------------------------------------------------------------
__global__ void __launch_bounds__(256)
softmax_kernel(const float* __restrict__ S,
               __nv_bfloat16* __restrict__ ph, __nv_bfloat16* __restrict__ pl)
{
    const long row = blockIdx.x;
    const float* p = S + row * (long)SEQ;
    const int t = threadIdx.x;
    __shared__ float red[8];

    float v[8];
    float m = -1e30f;
#pragma unroll
    for (int i = 0; i < 8; i++) {
        v[i] = p[t + i * 256];
        m = fmaxf(m, v[i]);
    }
#pragma unroll
    for (int o = 16; o > 0; o >>= 1)
        m = fmaxf(m, __shfl_xor_sync(0xffffffff, m, o));
    const int warp = t >> 5, lane = t & 31;
    if (lane == 0) red[warp] = m;
    __syncthreads();
    m = red[0];
#pragma unroll
    for (int w = 1; w < 8; w++) m = fmaxf(m, red[w]);
    __syncthreads();

    float s = 0.0f;
#pragma unroll
    for (int i = 0; i < 8; i++) {
        v[i] = __expf(v[i] - m);
        s += v[i];
    }
#pragma unroll
    for (int o = 16; o > 0; o >>= 1)
        s += __shfl_xor_sync(0xffffffff, s, o);
    if (lane == 0) red[warp] = s;
    __syncthreads();
    s = red[0];
#pragma unroll
    for (int w = 1; w < 8; w++) s += red[w];

    const float inv = 1.0f / s;
#pragma unroll
    for (int i = 0; i < 8; i++) {
        float f = v[i] * inv;
        __nv_bfloat16 h = bf_hi(f);
        const long a = row * (long)SEQ + t + i * 256;
        ph[a] = h;
        pl[a] = bf_lo(f, h);
    }
}

// ---------------------------------------------------------------------------
// Launch
// ---------------------------------------------------------------------------
extern "C" void kernel_launch(void* const* d_in, const int* in_sizes, int n_in,
                              void* d_out, int out_size)
{
    const float* x   = (const float*)d_in[0];   // [B, S, D]
    const float* QKV = (const float*)d_in[1];   // [3, D, D]
    float* out = (float*)d_out;                 // [B, S, D]

    __nv_bfloat16 *xh, *xl, *wth, *wtl, *qh, *ql, *kh, *kl, *vth, *vtl, *ph, *pl;
    float* s;
    cudaGetSymbolAddress((void**)&xh,  g_xh);
    cudaGetSymbolAddress((void**)&xl,  g_xl);
    cudaGetSymbolAddress((void**)&wth, g_wth);
    cudaGetSymbolAddress((void**)&wtl, g_wtl);
    cudaGetSymbolAddress((void**)&qh,  g_qh);
    cudaGetSymbolAddress((void**)&ql,  g_ql);
    cudaGetSymbolAddress((void**)&kh,  g_kh);
    cudaGetSymbolAddress((void**)&kl,  g_kl);
    cudaGetSymbolAddress((void**)&vth, g_vth);
    cudaGetSymbolAddress((void**)&vtl, g_vtl);
    cudaGetSymbolAddress((void**)&ph,  g_ph);
    cudaGetSymbolAddress((void**)&pl,  g_pl);
    cudaGetSymbolAddress((void**)&s,   g_s);

    cudaFuncSetAttribute(gemm_mma<0>, cudaFuncAttributeMaxDynamicSharedMemorySize, SMEM_TOTAL);
    cudaFuncSetAttribute(gemm_mma<1>, cudaFuncAttributeMaxDynamicSharedMemorySize, SMEM_TOTAL);
    cudaFuncSetAttribute(gemm_mma<2>, cudaFuncAttributeMaxDynamicSharedMemorySize, SMEM_TOTAL);

    const float scale = 1.0f / sqrtf((float)DIM);

    // 1) split x into bf16 hi/lo
    conv_x_kernel<<<(BATCH * SEQ * DIM) / 1024, 256>>>(x, xh, xl);
    // 2) transpose + split weights
    conv_w_kernel<<<dim3(DIM / 32, DIM / 32, 3), 256>>>(QKV, wth, wtl);

    // 3) QKV projection -> q,k (hi/lo, [b,s,d]) and V^T (hi/lo, [b,d,s])
    gemm_mma<0><<<dim3(DIM / 128, (BATCH * SEQ) / 128, 3), 256, SMEM_TOTAL>>>(
        xh, xl, wth, wtl, nullptr, qh, ql, kh, kl, vth, vtl, 1.0f);

    // 4) logits = scale * Q @ K^T
    gemm_mma<1><<<dim3(SEQ / 128, SEQ / 128, BATCH), 256, SMEM_TOTAL>>>(
        qh, ql, kh, kl, s, nullptr, nullptr, nullptr, nullptr, nullptr, nullptr,
        scale);

    // 5) softmax -> probs hi/lo
    softmax_kernel<<<BATCH * SEQ, 256>>>(s, ph, pl);

    // 6) out = P @ V
    gemm_mma<2><<<dim3(DIM / 128, SEQ / 128, BATCH), 256, SMEM_TOTAL>>>(
        ph, pl, vth, vtl, out, nullptr, nullptr, nullptr, nullptr, nullptr, nullptr,
        1.0f);
}

// round 4
// speedup vs baseline: 2.8738x; 1.2683x over previous
#include <cuda_runtime.h>
#include <cuda_bf16.h>
#include <math.h>
#include <stdint.h>

// ---------------------------------------------------------------------------
// Problem constants
// ---------------------------------------------------------------------------
#define BATCH 8
#define SEQ   2048
#define DIM   768

// ---------------------------------------------------------------------------
// Scratch (__device__ globals; no allocation allowed)
// ---------------------------------------------------------------------------
__device__ __nv_bfloat16 g_xh[(size_t)BATCH * SEQ * DIM];
__device__ __nv_bfloat16 g_xl[(size_t)BATCH * SEQ * DIM];
__device__ __nv_bfloat16 g_wth[3ULL * DIM * DIM];   // W^T per slice, [z][n][k]
__device__ __nv_bfloat16 g_wtl[3ULL * DIM * DIM];
__device__ __nv_bfloat16 g_qh[(size_t)BATCH * SEQ * DIM];
__device__ __nv_bfloat16 g_ql[(size_t)BATCH * SEQ * DIM];
__device__ __nv_bfloat16 g_kh[(size_t)BATCH * SEQ * DIM];
__device__ __nv_bfloat16 g_kl[(size_t)BATCH * SEQ * DIM];
__device__ __nv_bfloat16 g_vth[(size_t)BATCH * DIM * SEQ];  // V^T: [b][d][s]
__device__ __nv_bfloat16 g_vtl[(size_t)BATCH * DIM * SEQ];
__device__ float         g_s[(size_t)BATCH * SEQ * SEQ];    // fp32 logits
__device__ __nv_bfloat16 g_ph[(size_t)BATCH * SEQ * SEQ];   // probs hi/lo
__device__ __nv_bfloat16 g_pl[(size_t)BATCH * SEQ * SEQ];

// ---------------------------------------------------------------------------
// Helpers
// ---------------------------------------------------------------------------
__device__ __forceinline__ uint32_t smem_u32(const void* p) {
    uint32_t a;
    asm("{ .reg .u64 t; cvta.to.shared.u64 t, %1; cvt.u32.u64 %0, t; }"
        : "=r"(a) : "l"(p));
    return a;
}

__device__ __forceinline__ __nv_bfloat16 bf_hi(float f) {
    return __float2bfloat16_rn(f);
}
__device__ __forceinline__ __nv_bfloat16 bf_lo(float f, __nv_bfloat16 h) {
    return __float2bfloat16_rn(f - __bfloat162float(h));
}

#define LDSM4(r, addr) \
    asm volatile("ldmatrix.sync.aligned.m8n8.x4.shared.b16 {%0,%1,%2,%3}, [%4];" \
        : "=r"((r)[0]), "=r"((r)[1]), "=r"((r)[2]), "=r"((r)[3]) : "r"(addr))

#define MMA_BF16(d, a, b) \
    asm volatile("mma.sync.aligned.m16n8k16.row.col.f32.bf16.bf16.f32 " \
        "{%0,%1,%2,%3}, {%4,%5,%6,%7}, {%8,%9}, {%0,%1,%2,%3};" \
        : "+f"((d)[0]), "+f"((d)[1]), "+f"((d)[2]), "+f"((d)[3]) \
        : "r"((a)[0]), "r"((a)[1]), "r"((a)[2]), "r"((a)[3]), \
          "r"((b)[0]), "r"((b)[1]))

#define CP_ASYNC16(dst, src) \
    asm volatile("cp.async.cg.shared.global [%0], [%1], 16;" \
        :: "r"(dst), "l"(src))
#define CP_COMMIT()  asm volatile("cp.async.commit_group;")
#define CP_WAIT1()   asm volatile("cp.async.wait_group 1;")
#define CP_WAIT0()   asm volatile("cp.async.wait_group 0;")

// ---------------------------------------------------------------------------
// GEMM tiling: BM=128, BN=128, BK=32 bf16; 8 warps (2 m x 4 n), warp 64x32.
// SMEM per stage: 4 operand tiles (A_hi, A_lo, B_hi, B_lo), each 128 rows x
// 32 bf16 = 64B/row, XOR-swizzled (chunk ^= (row>>1)&3): zero padding,
// conflict-free for both cp.async 16B stores and ldmatrix 8-lane phases.
// Tile 8KB -> stage 32KB -> 64KB total => 2 CTAs/SM (regs capped at 128).
// ---------------------------------------------------------------------------
#define TILE_B  8192
#define STAGE_B (4 * TILE_B)             // 32768
#define SMEM_TOTAL (2 * STAGE_B)         // 65536

__device__ __forceinline__ uint32_t sw_off(int row, int chunk) {
    return (uint32_t)(row * 64 + ((chunk ^ ((row >> 1) & 3)) << 4));
}

// MODE 0: QKV proj (K=768;  z = weight slice; -> q/k hi/lo, V^T hi/lo)
// MODE 1: Q @ K^T  (K=768;  z = batch; -> fp32 logits * alpha)
// MODE 2: P @ V^T  (K=2048; z = batch; -> fp32 d_out)
template <int MODE>
__global__ void __launch_bounds__(256, 2)
gemm_mma(const __nv_bfloat16* __restrict__ Ah, const __nv_bfloat16* __restrict__ Al,
         const __nv_bfloat16* __restrict__ Bh, const __nv_bfloat16* __restrict__ Bl,
         float* __restrict__ outF,
         __nv_bfloat16* __restrict__ o0h, __nv_bfloat16* __restrict__ o0l,
         __nv_bfloat16* __restrict__ o1h, __nv_bfloat16* __restrict__ o1l,
         __nv_bfloat16* __restrict__ o2h, __nv_bfloat16* __restrict__ o2l,
         float alpha)
{
    constexpr int  K  = (MODE == 2) ? 2048 : 768;
    constexpr long sA = (MODE == 0) ? 0L
                       : (MODE == 1) ? (long)SEQ * DIM : (long)SEQ * SEQ;
    constexpr long sB = (MODE == 0) ? (long)DIM * DIM
                       : (MODE == 1) ? (long)SEQ * DIM : (long)DIM * SEQ;
    constexpr int NC  = K / 32;

    extern __shared__ char smem[];
    const uint32_t sbase = smem_u32(smem);

    const int tid  = threadIdx.x;
    const int wid  = tid >> 5;
    const int lane = tid & 31;
    const int wm   = wid & 1;      // 0..1
    const int wn   = wid >> 1;     // 0..3
    const int z    = blockIdx.z;
    const int bm   = blockIdx.y * 128;
    const int bn   = blockIdx.x * 128;

    const __nv_bfloat16* gA[2] = { Ah + (long)z * sA + (long)bm * K,
                                   Al + (long)z * sA + (long)bm * K };
    const __nv_bfloat16* gB[2] = { Bh + (long)z * sB + (long)bn * K,
                                   Bl + (long)z * sB + (long)bn * K };

    // Per-thread gmem load coords: 512 16B-chunks per tile (128 rows x 4); 2 per thread.
    const int l_row0 = (tid + 0)   >> 2, l_c0 = (tid + 0)   & 3;
    const int l_row1 = (tid + 256) >> 2, l_c1 = (tid + 256) & 3;
    const uint32_t so0 = sw_off(l_row0, l_c0);
    const uint32_t so1 = sw_off(l_row1, l_c1);

    auto load_stage = [&](int buf, int k0) {
        const uint32_t soff = sbase + buf * STAGE_B;
#pragma unroll
        for (int op = 0; op < 4; op++) {
            const __nv_bfloat16* g = (op < 2) ? gA[op] : gB[op - 2];
            CP_ASYNC16(soff + op * TILE_B + so0, g + (long)l_row0 * K + k0 + l_c0 * 8);
            CP_ASYNC16(soff + op * TILE_B + so1, g + (long)l_row1 * K + k0 + l_c1 * 8);
        }
        CP_COMMIT();
    };

    // ldmatrix per-thread addressing
    const int rA = lane & 15;                          // A row within 16
    const int chA = lane >> 4;                         // 0 or 1 (16B chunk in k)
    const int rB = (lane & 7) | ((lane >> 4) << 3);    // B row within 16 (n)
    const int chB = (lane >> 3) & 1;                   // 0 or 1 (16B chunk in k)

    float acc[4][4][4];
#pragma unroll
    for (int mf = 0; mf < 4; mf++)
#pragma unroll
        for (int nf = 0; nf < 4; nf++)
#pragma unroll
            for (int q = 0; q < 4; q++) acc[mf][nf][q] = 0.0f;

    load_stage(0, 0);

    for (int c = 0; c < NC; c++) {
        if (c + 1 < NC) { load_stage((c + 1) & 1, (c + 1) * 32); CP_WAIT1(); }
        else            { CP_WAIT0(); }
        __syncthreads();

        const uint32_t soff = sbase + (c & 1) * STAGE_B;
        const uint32_t aH = soff + 0 * TILE_B;
        const uint32_t aL = soff + 1 * TILE_B;
        const uint32_t bH = soff + 2 * TILE_B;
        const uint32_t bL = soff + 3 * TILE_B;

#pragma unroll
        for (int ks = 0; ks < 2; ks++) {
            uint32_t ah[4][4], al[4][4], bh[4][2], bl[4][2];
#pragma unroll
            for (int mf = 0; mf < 4; mf++) {
                const int row = wm * 64 + mf * 16 + rA;
                const uint32_t ro = sw_off(row, ks * 2 + chA);
                LDSM4(ah[mf], aH + ro);
                LDSM4(al[mf], aL + ro);
            }
#pragma unroll
            for (int nf2 = 0; nf2 < 2; nf2++) {
                const int row = wn * 32 + nf2 * 16 + rB;
                const uint32_t ro = sw_off(row, ks * 2 + chB);
                uint32_t th[4], tl[4];
                LDSM4(th, bH + ro);
                LDSM4(tl, bL + ro);
                bh[nf2 * 2][0] = th[0]; bh[nf2 * 2][1] = th[1];
                bh[nf2 * 2 + 1][0] = th[2]; bh[nf2 * 2 + 1][1] = th[3];
                bl[nf2 * 2][0] = tl[0]; bl[nf2 * 2][1] = tl[1];
                bl[nf2 * 2 + 1][0] = tl[2]; bl[nf2 * 2 + 1][1] = tl[3];
            }
#pragma unroll
            for (int mf = 0; mf < 4; mf++)
#pragma unroll
                for (int nf = 0; nf < 4; nf++) {
                    MMA_BF16(acc[mf][nf], ah[mf], bh[nf]);
                    MMA_BF16(acc[mf][nf], ah[mf], bl[nf]);
                    MMA_BF16(acc[mf][nf], al[mf], bh[nf]);
                }
        }
        __syncthreads();
    }

    // -----------------------------------------------------------------------
    // Epilogue: thread owns (r0, n0..n0+1) and (r0+8, n0..n0+1) per frag.
    // -----------------------------------------------------------------------
    const int gq = lane >> 2;
    const int i2 = (lane & 3) * 2;

#pragma unroll
    for (int mf = 0; mf < 4; mf++) {
#pragma unroll
        for (int nf = 0; nf < 4; nf++) {
            const int n0 = bn + wn * 32 + nf * 8 + i2;
#pragma unroll
            for (int h = 0; h < 2; h++) {
                const int mg = bm + wm * 64 + mf * 16 + gq + h * 8;
                const float f0 = acc[mf][nf][h * 2 + 0];
                const float f1 = acc[mf][nf][h * 2 + 1];

                if (MODE == 0) {
                    if (z < 2) {
                        __nv_bfloat16* dh = (z == 0) ? o0h : o1h;
                        __nv_bfloat16* dl = (z == 0) ? o0l : o1l;
                        __nv_bfloat16 h0 = bf_hi(f0), h1 = bf_hi(f1);
                        __nv_bfloat16 l0 = bf_lo(f0, h0), l1 = bf_lo(f1, h1);
                        const long addr = (long)mg * DIM + n0;
                        __nv_bfloat162 hv; hv.x = h0; hv.y = h1;
                        __nv_bfloat162 lv; lv.x = l0; lv.y = l1;
                        *reinterpret_cast<__nv_bfloat162*>(dh + addr) = hv;
                        *reinterpret_cast<__nv_bfloat162*>(dl + addr) = lv;
                    } else {
                        // V: write transposed V^T[b][d][s]
                        const int b = mg >> 11;
                        const int s = mg & 2047;
                        __nv_bfloat16 h0 = bf_hi(f0), h1 = bf_hi(f1);
                        const long a0 = ((long)b * DIM + n0) * SEQ + s;
                        const long a1 = ((long)b * DIM + n0 + 1) * SEQ + s;
                        o2h[a0] = h0; o2l[a0] = bf_lo(f0, h0);
                        o2h[a1] = h1; o2l[a1] = bf_lo(f1, h1);
                    }
                } else if (MODE == 1) {
                    float* dst = outF + (long)z * SEQ * SEQ + (long)mg * SEQ + n0;
                    float2 v = make_float2(f0 * alpha, f1 * alpha);
                    *reinterpret_cast<float2*>(dst) = v;
                } else {
                    float* dst = outF + (long)z * SEQ * DIM + (long)mg * DIM + n0;
                    float2 v = make_float2(f0, f1);
                    *reinterpret_cast<float2*>(dst) = v;
                }
            }
        }
    }
}

// ---------------------------------------------------------------------------
// Conversion kernels
// ---------------------------------------------------------------------------
__global__ void __launch_bounds__(256)
conv_x_kernel(const float* __restrict__ x,
              __nv_bfloat16* __restrict__ xh, __nv_bfloat16* __restrict__ xl)
{
    const long i = ((long)blockIdx.x * 256 + threadIdx.x) * 4;
    float4 v = *reinterpret_cast<const float4*>(x + i);
    __nv_bfloat16 h[4], l[4];
    h[0] = bf_hi(v.x); l[0] = bf_lo(v.x, h[0]);
    h[1] = bf_hi(v.y); l[1] = bf_lo(v.y, h[1]);
    h[2] = bf_hi(v.z); l[2] = bf_lo(v.z, h[2]);
    h[3] = bf_hi(v.w); l[3] = bf_lo(v.w, h[3]);
    *reinterpret_cast<uint2*>(xh + i) = *reinterpret_cast<uint2*>(h);
    *reinterpret_cast<uint2*>(xl + i) = *reinterpret_cast<uint2*>(l);
}

// Transpose + split QKV weights: W[z][k][n] -> Wt[z][n][k]
__global__ void __launch_bounds__(256)
conv_w_kernel(const float* __restrict__ W,
              __nv_bfloat16* __restrict__ wth, __nv_bfloat16* __restrict__ wtl)
{
    __shared__ float tile[32][33];
    const int z  = blockIdx.z;
    const int bx = blockIdx.x * 32;   // n
    const int by = blockIdx.y * 32;   // k
    const int tx = threadIdx.x & 31;
    const int ty = threadIdx.x >> 5;  // 0..7
    const float* Wz = W + (long)z * DIM * DIM;
#pragma unroll
    for (int i = 0; i < 32; i += 8)
        tile[ty + i][tx] = Wz[(long)(by + ty + i) * DIM + (bx + tx)];
    __syncthreads();
    __nv_bfloat16* th = wth + (long)z * DIM * DIM;
    __nv_bfloat16* tl = wtl + (long)z * DIM * DIM;
#pragma unroll
    for (int i = 0; i < 32; i += 8) {
        float f = tile[tx][ty + i];
        __nv_bfloat16 h = bf_hi(f);
        const long addr = (long)(bx + ty + i) * DIM + (by + tx);
        th[addr] = h;
        tl[addr] = bf_lo(f, h);
    }
}

// ---------------------------------------------------------------------------
// Softmax: fp32 logits row -> bf16 hi/lo probs
// ---------------------------------------------------------------------------
__global__ void __launch_bounds__(256)
softmax_kernel(const float* __restrict__ S,
               __nv_bfloat16* __restrict__ ph, __nv_bfloat16* __restrict__ pl)
{
    const long row = blockIdx.x;
    const float* p = S + row * (long)SEQ;
    const int t = threadIdx.x;
    __shared__ float red[8];

    float v[8];
    float m = -1e30f;
#pragma unroll
    for (int i = 0; i < 8; i++) {
        v[i] = p[t + i * 256];
        m = fmaxf(m, v[i]);
    }
#pragma unroll
    for (int o = 16; o > 0; o >>= 1)
        m = fmaxf(m, __shfl_xor_sync(0xffffffff, m, o));
    const int warp = t >> 5, lane = t & 31;
    if (lane == 0) red[warp] = m;
    __syncthreads();
    m = red[0];
#pragma unroll
    for (int w = 1; w < 8; w++) m = fmaxf(m, red[w]);
    __syncthreads();

    float s = 0.0f;
#pragma unroll
    for (int i = 0; i < 8; i++) {
        v[i] = __expf(v[i] - m);
        s += v[i];
    }
#pragma unroll
    for (int o = 16; o > 0; o >>= 1)
        s += __shfl_xor_sync(0xffffffff, s, o);
    if (lane == 0) red[warp] = s;
    __syncthreads();
    s = red[0];
#pragma unroll
    for (int w = 1; w < 8; w++) s += red[w];

    const float inv = 1.0f / s;
#pragma unroll
    for (int i = 0; i < 8; i++) {
        float f = v[i] * inv;
        __nv_bfloat16 h = bf_hi(f);
        const long a = row * (long)SEQ + t + i * 256;
        ph[a] = h;
        pl[a] = bf_lo(f, h);
    }
}

// ---------------------------------------------------------------------------
// Launch
// ---------------------------------------------------------------------------
extern "C" void kernel_launch(void* const* d_in, const int* in_sizes, int n_in,
                              void* d_out, int out_size)
{
    const float* x   = (const float*)d_in[0];   // [B, S, D]
    const float* QKV = (const float*)d_in[1];   // [3, D, D]
    float* out = (float*)d_out;                 // [B, S, D]

    __nv_bfloat16 *xh, *xl, *wth, *wtl, *qh, *ql, *kh, *kl, *vth, *vtl, *ph, *pl;
    float* s;
    cudaGetSymbolAddress((void**)&xh,  g_xh);
    cudaGetSymbolAddress((void**)&xl,  g_xl);
    cudaGetSymbolAddress((void**)&wth, g_wth);
    cudaGetSymbolAddress((void**)&wtl, g_wtl);
    cudaGetSymbolAddress((void**)&qh,  g_qh);
    cudaGetSymbolAddress((void**)&ql,  g_ql);
    cudaGetSymbolAddress((void**)&kh,  g_kh);
    cudaGetSymbolAddress((void**)&kl,  g_kl);
    cudaGetSymbolAddress((void**)&vth, g_vth);
    cudaGetSymbolAddress((void**)&vtl, g_vtl);
    cudaGetSymbolAddress((void**)&ph,  g_ph);
    cudaGetSymbolAddress((void**)&pl,  g_pl);
    cudaGetSymbolAddress((void**)&s,   g_s);

    cudaFuncSetAttribute(gemm_mma<0>, cudaFuncAttributeMaxDynamicSharedMemorySize, SMEM_TOTAL);
    cudaFuncSetAttribute(gemm_mma<1>, cudaFuncAttributeMaxDynamicSharedMemorySize, SMEM_TOTAL);
    cudaFuncSetAttribute(gemm_mma<2>, cudaFuncAttributeMaxDynamicSharedMemorySize, SMEM_TOTAL);

    const float scale = 1.0f / sqrtf((float)DIM);

    // 1) split x into bf16 hi/lo
    conv_x_kernel<<<(BATCH * SEQ * DIM) / 1024, 256>>>(x, xh, xl);
    // 2) transpose + split weights
    conv_w_kernel<<<dim3(DIM / 32, DIM / 32, 3), 256>>>(QKV, wth, wtl);

    // 3) QKV projection -> q,k (hi/lo, [b,s,d]) and V^T (hi/lo, [b,d,s])
    gemm_mma<0><<<dim3(DIM / 128, (BATCH * SEQ) / 128, 3), 256, SMEM_TOTAL>>>(
        xh, xl, wth, wtl, nullptr, qh, ql, kh, kl, vth, vtl, 1.0f);

    // 4) logits = scale * Q @ K^T
    gemm_mma<1><<<dim3(SEQ / 128, SEQ / 128, BATCH), 256, SMEM_TOTAL>>>(
        qh, ql, kh, kl, s, nullptr, nullptr, nullptr, nullptr, nullptr, nullptr,
        scale);

    // 5) softmax -> probs hi/lo
    softmax_kernel<<<BATCH * SEQ, 256>>>(s, ph, pl);

    // 6) out = P @ V
    gemm_mma<2><<<dim3(DIM / 128, SEQ / 128, BATCH), 256, SMEM_TOTAL>>>(
        ph, pl, vth, vtl, out, nullptr, nullptr, nullptr, nullptr, nullptr, nullptr,
        1.0f);
}

// round 5
// speedup vs baseline: 2.9132x; 1.0137x over previous
#include <cuda_runtime.h>
#include <cuda_bf16.h>
#include <math.h>
#include <stdint.h>

// ---------------------------------------------------------------------------
// Problem constants
// ---------------------------------------------------------------------------
#define BATCH 8
#define SEQ   2048
#define DIM   768

// ---------------------------------------------------------------------------
// Scratch (__device__ globals; no allocation allowed)
// ---------------------------------------------------------------------------
__device__ __nv_bfloat16 g_xh[(size_t)BATCH * SEQ * DIM];
__device__ __nv_bfloat16 g_xl[(size_t)BATCH * SEQ * DIM];
__device__ __nv_bfloat16 g_wth[3ULL * DIM * DIM];   // W^T per slice, [z][n][k]
__device__ __nv_bfloat16 g_wtl[3ULL * DIM * DIM];
__device__ __nv_bfloat16 g_qh[(size_t)BATCH * SEQ * DIM];
__device__ __nv_bfloat16 g_ql[(size_t)BATCH * SEQ * DIM];
__device__ __nv_bfloat16 g_kh[(size_t)BATCH * SEQ * DIM];
__device__ __nv_bfloat16 g_kl[(size_t)BATCH * SEQ * DIM];
__device__ __nv_bfloat16 g_vth[(size_t)BATCH * DIM * SEQ];  // V^T: [b][d][s]
__device__ __nv_bfloat16 g_vtl[(size_t)BATCH * DIM * SEQ];
__device__ float         g_s[(size_t)BATCH * SEQ * SEQ];    // fp32 logits
__device__ __nv_bfloat16 g_ph[(size_t)BATCH * SEQ * SEQ];   // probs hi/lo
__device__ __nv_bfloat16 g_pl[(size_t)BATCH * SEQ * SEQ];

// ---------------------------------------------------------------------------
// Helpers
// ---------------------------------------------------------------------------
__device__ __forceinline__ uint32_t smem_u32(const void* p) {
    uint32_t a;
    asm("{ .reg .u64 t; cvta.to.shared.u64 t, %1; cvt.u32.u64 %0, t; }"
        : "=r"(a) : "l"(p));
    return a;
}

__device__ __forceinline__ __nv_bfloat16 bf_hi(float f) {
    return __float2bfloat16_rn(f);
}
__device__ __forceinline__ __nv_bfloat16 bf_lo(float f, __nv_bfloat16 h) {
    return __float2bfloat16_rn(f - __bfloat162float(h));
}

#define LDSM4(r, addr) \
    asm volatile("ldmatrix.sync.aligned.m8n8.x4.shared.b16 {%0,%1,%2,%3}, [%4];" \
        : "=r"((r)[0]), "=r"((r)[1]), "=r"((r)[2]), "=r"((r)[3]) : "r"(addr))

#define MMA_BF16(d, a, b) \
    asm volatile("mma.sync.aligned.m16n8k16.row.col.f32.bf16.bf16.f32 " \
        "{%0,%1,%2,%3}, {%4,%5,%6,%7}, {%8,%9}, {%0,%1,%2,%3};" \
        : "+f"((d)[0]), "+f"((d)[1]), "+f"((d)[2]), "+f"((d)[3]) \
        : "r"((a)[0]), "r"((a)[1]), "r"((a)[2]), "r"((a)[3]), \
          "r"((b)[0]), "r"((b)[1]))

#define CP_ASYNC16(dst, src) \
    asm volatile("cp.async.cg.shared.global [%0], [%1], 16;" \
        :: "r"(dst), "l"(src))
#define CP_COMMIT()  asm volatile("cp.async.commit_group;")
#define CP_WAIT1()   asm volatile("cp.async.wait_group 1;")
#define CP_WAIT0()   asm volatile("cp.async.wait_group 0;")

// ---------------------------------------------------------------------------
// GEMM tiling: BM=128, BN=128, BK=32 bf16; 8 warps (2 m x 4 n), warp 64x32.
// SMEM per stage: 4 operand tiles (A_hi, A_lo, B_hi, B_lo), each 128 rows x
// 32 bf16 = 64B/row, XOR-swizzled (chunk ^= (row>>1)&3): zero padding,
// conflict-free for both cp.async 16B stores and ldmatrix 8-lane phases.
// 3-stage ring (96KB/CTA) + 1 barrier per chunk; 2 CTAs/SM (192KB, 128 regs).
// ---------------------------------------------------------------------------
#define TILE_B  8192
#define STAGE_B (4 * TILE_B)             // 32768
#define NSTAGE  3
#define SMEM_TOTAL (NSTAGE * STAGE_B)    // 98304

__device__ __forceinline__ uint32_t sw_off(int row, int chunk) {
    return (uint32_t)(row * 64 + ((chunk ^ ((row >> 1) & 3)) << 4));
}

// MODE 0: QKV proj (K=768;  z = weight slice; -> q/k hi/lo, V^T hi/lo)
// MODE 1: Q @ K^T  (K=768;  z = batch; -> fp32 logits * alpha)
// MODE 2: P @ V^T  (K=2048; z = batch; -> fp32 d_out)
template <int MODE>
__global__ void __launch_bounds__(256, 2)
gemm_mma(const __nv_bfloat16* __restrict__ Ah, const __nv_bfloat16* __restrict__ Al,
         const __nv_bfloat16* __restrict__ Bh, const __nv_bfloat16* __restrict__ Bl,
         float* __restrict__ outF,
         __nv_bfloat16* __restrict__ o0h, __nv_bfloat16* __restrict__ o0l,
         __nv_bfloat16* __restrict__ o1h, __nv_bfloat16* __restrict__ o1l,
         __nv_bfloat16* __restrict__ o2h, __nv_bfloat16* __restrict__ o2l,
         float alpha)
{
    constexpr int  K  = (MODE == 2) ? 2048 : 768;
    constexpr long sA = (MODE == 0) ? 0L
                       : (MODE == 1) ? (long)SEQ * DIM : (long)SEQ * SEQ;
    constexpr long sB = (MODE == 0) ? (long)DIM * DIM
                       : (MODE == 1) ? (long)SEQ * DIM : (long)DIM * SEQ;
    constexpr int NC  = K / 32;

    extern __shared__ char smem[];
    const uint32_t sbase = smem_u32(smem);

    const int tid  = threadIdx.x;
    const int wid  = tid >> 5;
    const int lane = tid & 31;
    const int wm   = wid & 1;      // 0..1
    const int wn   = wid >> 1;     // 0..3
    const int z    = blockIdx.z;
    const int bm   = blockIdx.y * 128;
    const int bn   = blockIdx.x * 128;

    const __nv_bfloat16* gA[2] = { Ah + (long)z * sA + (long)bm * K,
                                   Al + (long)z * sA + (long)bm * K };
    const __nv_bfloat16* gB[2] = { Bh + (long)z * sB + (long)bn * K,
                                   Bl + (long)z * sB + (long)bn * K };

    // Per-thread gmem load coords: 512 16B-chunks per tile (128 rows x 4); 2 per thread.
    const int l_row0 = (tid + 0)   >> 2, l_c0 = (tid + 0)   & 3;
    const int l_row1 = (tid + 256) >> 2, l_c1 = (tid + 256) & 3;
    const uint32_t so0 = sw_off(l_row0, l_c0);
    const uint32_t so1 = sw_off(l_row1, l_c1);

    auto load_stage = [&](int slot, int k0) {
        const uint32_t soff = sbase + slot * STAGE_B;
#pragma unroll
        for (int op = 0; op < 4; op++) {
            const __nv_bfloat16* g = (op < 2) ? gA[op] : gB[op - 2];
            CP_ASYNC16(soff + op * TILE_B + so0, g + (long)l_row0 * K + k0 + l_c0 * 8);
            CP_ASYNC16(soff + op * TILE_B + so1, g + (long)l_row1 * K + k0 + l_c1 * 8);
        }
        CP_COMMIT();
    };

    // ldmatrix per-thread addressing
    const int rA = lane & 15;                          // A row within 16
    const int chA = lane >> 4;                         // 0 or 1 (16B chunk in k)
    const int rB = (lane & 7) | ((lane >> 4) << 3);    // B row within 16 (n)
    const int chB = (lane >> 3) & 1;                   // 0 or 1 (16B chunk in k)

    float acc[4][4][4];
#pragma unroll
    for (int mf = 0; mf < 4; mf++)
#pragma unroll
        for (int nf = 0; nf < 4; nf++)
#pragma unroll
            for (int q = 0; q < 4; q++) acc[mf][nf][q] = 0.0f;

    // Prologue: stages 0 and 1 in flight.
    load_stage(0, 0);
    load_stage(1, 32);

    int slot = 0;
    for (int c = 0; c < NC; c++) {
        // Wait for stage c to land (2 groups pending -> keep 1; last iter -> 0).
        if (c + 1 < NC) { CP_WAIT1(); } else { CP_WAIT0(); }
        // Single barrier: publishes stage c to all warps AND licenses
        // overwriting slot (c+2)%3 (its last readers finished iter c-1).
        __syncthreads();
        if (c + 2 < NC) {
            const int ns = (slot + 2 >= NSTAGE) ? slot + 2 - NSTAGE : slot + 2;
            load_stage(ns, (c + 2) * 32);
        }

        const uint32_t soff = sbase + slot * STAGE_B;
        const uint32_t aH = soff + 0 * TILE_B;
        const uint32_t aL = soff + 1 * TILE_B;
        const uint32_t bH = soff + 2 * TILE_B;
        const uint32_t bL = soff + 3 * TILE_B;

#pragma unroll
        for (int ks = 0; ks < 2; ks++) {
            uint32_t ah[4][4], al[4][4], bh[4][2], bl[4][2];
#pragma unroll
            for (int mf = 0; mf < 4; mf++) {
                const int row = wm * 64 + mf * 16 + rA;
                const uint32_t ro = sw_off(row, ks * 2 + chA);
                LDSM4(ah[mf], aH + ro);
                LDSM4(al[mf], aL + ro);
            }
#pragma unroll
            for (int nf2 = 0; nf2 < 2; nf2++) {
                const int row = wn * 32 + nf2 * 16 + rB;
                const uint32_t ro = sw_off(row, ks * 2 + chB);
                uint32_t th[4], tl[4];
                LDSM4(th, bH + ro);
                LDSM4(tl, bL + ro);
                bh[nf2 * 2][0] = th[0]; bh[nf2 * 2][1] = th[1];
                bh[nf2 * 2 + 1][0] = th[2]; bh[nf2 * 2 + 1][1] = th[3];
                bl[nf2 * 2][0] = tl[0]; bl[nf2 * 2][1] = tl[1];
                bl[nf2 * 2 + 1][0] = tl[2]; bl[nf2 * 2 + 1][1] = tl[3];
            }
#pragma unroll
            for (int mf = 0; mf < 4; mf++)
#pragma unroll
                for (int nf = 0; nf < 4; nf++) {
                    MMA_BF16(acc[mf][nf], ah[mf], bh[nf]);
                    MMA_BF16(acc[mf][nf], ah[mf], bl[nf]);
                    MMA_BF16(acc[mf][nf], al[mf], bh[nf]);
                }
        }

        slot = (slot + 1 >= NSTAGE) ? 0 : slot + 1;
    }

    // -----------------------------------------------------------------------
    // Epilogue: thread owns (r0, n0..n0+1) and (r0+8, n0..n0+1) per frag.
    // -----------------------------------------------------------------------
    const int gq = lane >> 2;
    const int i2 = (lane & 3) * 2;

#pragma unroll
    for (int mf = 0; mf < 4; mf++) {
#pragma unroll
        for (int nf = 0; nf < 4; nf++) {
            const int n0 = bn + wn * 32 + nf * 8 + i2;
#pragma unroll
            for (int h = 0; h < 2; h++) {
                const int mg = bm + wm * 64 + mf * 16 + gq + h * 8;
                const float f0 = acc[mf][nf][h * 2 + 0];
                const float f1 = acc[mf][nf][h * 2 + 1];

                if (MODE == 0) {
                    if (z < 2) {
                        __nv_bfloat16* dh = (z == 0) ? o0h : o1h;
                        __nv_bfloat16* dl = (z == 0) ? o0l : o1l;
                        __nv_bfloat16 h0 = bf_hi(f0), h1 = bf_hi(f1);
                        __nv_bfloat16 l0 = bf_lo(f0, h0), l1 = bf_lo(f1, h1);
                        const long addr = (long)mg * DIM + n0;
                        __nv_bfloat162 hv; hv.x = h0; hv.y = h1;
                        __nv_bfloat162 lv; lv.x = l0; lv.y = l1;
                        *reinterpret_cast<__nv_bfloat162*>(dh + addr) = hv;
                        *reinterpret_cast<__nv_bfloat162*>(dl + addr) = lv;
                    } else {
                        // V: write transposed V^T[b][d][s]
                        const int b = mg >> 11;
                        const int s = mg & 2047;
                        __nv_bfloat16 h0 = bf_hi(f0), h1 = bf_hi(f1);
                        const long a0 = ((long)b * DIM + n0) * SEQ + s;
                        const long a1 = ((long)b * DIM + n0 + 1) * SEQ + s;
                        o2h[a0] = h0; o2l[a0] = bf_lo(f0, h0);
                        o2h[a1] = h1; o2l[a1] = bf_lo(f1, h1);
                    }
                } else if (MODE == 1) {
                    float* dst = outF + (long)z * SEQ * SEQ + (long)mg * SEQ + n0;
                    float2 v = make_float2(f0 * alpha, f1 * alpha);
                    *reinterpret_cast<float2*>(dst) = v;
                } else {
                    float* dst = outF + (long)z * SEQ * DIM + (long)mg * DIM + n0;
                    float2 v = make_float2(f0, f1);
                    *reinterpret_cast<float2*>(dst) = v;
                }
            }
        }
    }
}

// ---------------------------------------------------------------------------
// Conversion kernels
// ---------------------------------------------------------------------------
__global__ void __launch_bounds__(256)
conv_x_kernel(const float* __restrict__ x,
              __nv_bfloat16* __restrict__ xh, __nv_bfloat16* __restrict__ xl)
{
    const long i = ((long)blockIdx.x * 256 + threadIdx.x) * 4;
    float4 v = *reinterpret_cast<const float4*>(x + i);
    __nv_bfloat16 h[4], l[4];
    h[0] = bf_hi(v.x); l[0] = bf_lo(v.x, h[0]);
    h[1] = bf_hi(v.y); l[1] = bf_lo(v.y, h[1]);
    h[2] = bf_hi(v.z); l[2] = bf_lo(v.z, h[2]);
    h[3] = bf_hi(v.w); l[3] = bf_lo(v.w, h[3]);
    *reinterpret_cast<uint2*>(xh + i) = *reinterpret_cast<uint2*>(h);
    *reinterpret_cast<uint2*>(xl + i) = *reinterpret_cast<uint2*>(l);
}

// Transpose + split QKV weights: W[z][k][n] -> Wt[z][n][k]
__global__ void __launch_bounds__(256)
conv_w_kernel(const float* __restrict__ W,
              __nv_bfloat16* __restrict__ wth, __nv_bfloat16* __restrict__ wtl)
{
    __shared__ float tile[32][33];
    const int z  = blockIdx.z;
    const int bx = blockIdx.x * 32;   // n
    const int by = blockIdx.y * 32;   // k
    const int tx = threadIdx.x & 31;
    const int ty = threadIdx.x >> 5;  // 0..7
    const float* Wz = W + (long)z * DIM * DIM;
#pragma unroll
    for (int i = 0; i < 32; i += 8)
        tile[ty + i][tx] = Wz[(long)(by + ty + i) * DIM + (bx + tx)];
    __syncthreads();
    __nv_bfloat16* th = wth + (long)z * DIM * DIM;
    __nv_bfloat16* tl = wtl + (long)z * DIM * DIM;
#pragma unroll
    for (int i = 0; i < 32; i += 8) {
        float f = tile[tx][ty + i];
        __nv_bfloat16 h = bf_hi(f);
        const long addr = (long)(bx + ty + i) * DIM + (by + tx);
        th[addr] = h;
        tl[addr] = bf_lo(f, h);
    }
}

// ---------------------------------------------------------------------------
// Softmax: fp32 logits row -> bf16 hi/lo probs
// ---------------------------------------------------------------------------
__global__ void __launch_bounds__(256)
softmax_kernel(const float* __restrict__ S,
               __nv_bfloat16* __restrict__ ph, __nv_bfloat16* __restrict__ pl)
{
    const long row = blockIdx.x;
    const float* p = S + row * (long)SEQ;
    const int t = threadIdx.x;
    __shared__ float red[8];

    float v[8];
    float m = -1e30f;
#pragma unroll
    for (int i = 0; i < 8; i++) {
        v[i] = p[t + i * 256];
        m = fmaxf(m, v[i]);
    }
#pragma unroll
    for (int o = 16; o > 0; o >>= 1)
        m = fmaxf(m, __shfl_xor_sync(0xffffffff, m, o));
    const int warp = t >> 5, lane = t & 31;
    if (lane == 0) red[warp] = m;
    __syncthreads();
    m = red[0];
#pragma unroll
    for (int w = 1; w < 8; w++) m = fmaxf(m, red[w]);
    __syncthreads();

    float s = 0.0f;
#pragma unroll
    for (int i = 0; i < 8; i++) {
        v[i] = __expf(v[i] - m);
        s += v[i];
    }
#pragma unroll
    for (int o = 16; o > 0; o >>= 1)
        s += __shfl_xor_sync(0xffffffff, s, o);
    if (lane == 0) red[warp] = s;
    __syncthreads();
    s = red[0];
#pragma unroll
    for (int w = 1; w < 8; w++) s += red[w];

    const float inv = 1.0f / s;
#pragma unroll
    for (int i = 0; i < 8; i++) {
        float f = v[i] * inv;
        __nv_bfloat16 h = bf_hi(f);
        const long a = row * (long)SEQ + t + i * 256;
        ph[a] = h;
        pl[a] = bf_lo(f, h);
    }
}

// ---------------------------------------------------------------------------
// Launch
// ---------------------------------------------------------------------------
extern "C" void kernel_launch(void* const* d_in, const int* in_sizes, int n_in,
                              void* d_out, int out_size)
{
    const float* x   = (const float*)d_in[0];   // [B, S, D]
    const float* QKV = (const float*)d_in[1];   // [3, D, D]
    float* out = (float*)d_out;                 // [B, S, D]

    __nv_bfloat16 *xh, *xl, *wth, *wtl, *qh, *ql, *kh, *kl, *vth, *vtl, *ph, *pl;
    float* s;
    cudaGetSymbolAddress((void**)&xh,  g_xh);
    cudaGetSymbolAddress((void**)&xl,  g_xl);
    cudaGetSymbolAddress((void**)&wth, g_wth);
    cudaGetSymbolAddress((void**)&wtl, g_wtl);
    cudaGetSymbolAddress((void**)&qh,  g_qh);
    cudaGetSymbolAddress((void**)&ql,  g_ql);
    cudaGetSymbolAddress((void**)&kh,  g_kh);
    cudaGetSymbolAddress((void**)&kl,  g_kl);
    cudaGetSymbolAddress((void**)&vth, g_vth);
    cudaGetSymbolAddress((void**)&vtl, g_vtl);
    cudaGetSymbolAddress((void**)&ph,  g_ph);
    cudaGetSymbolAddress((void**)&pl,  g_pl);
    cudaGetSymbolAddress((void**)&s,   g_s);

    cudaFuncSetAttribute(gemm_mma<0>, cudaFuncAttributeMaxDynamicSharedMemorySize, SMEM_TOTAL);
    cudaFuncSetAttribute(gemm_mma<1>, cudaFuncAttributeMaxDynamicSharedMemorySize, SMEM_TOTAL);
    cudaFuncSetAttribute(gemm_mma<2>, cudaFuncAttributeMaxDynamicSharedMemorySize, SMEM_TOTAL);

    const float scale = 1.0f / sqrtf((float)DIM);

    // 1) split x into bf16 hi/lo
    conv_x_kernel<<<(BATCH * SEQ * DIM) / 1024, 256>>>(x, xh, xl);
    // 2) transpose + split weights
    conv_w_kernel<<<dim3(DIM / 32, DIM / 32, 3), 256>>>(QKV, wth, wtl);

    // 3) QKV projection -> q,k (hi/lo, [b,s,d]) and V^T (hi/lo, [b,d,s])
    gemm_mma<0><<<dim3(DIM / 128, (BATCH * SEQ) / 128, 3), 256, SMEM_TOTAL>>>(
        xh, xl, wth, wtl, nullptr, qh, ql, kh, kl, vth, vtl, 1.0f);

    // 4) logits = scale * Q @ K^T
    gemm_mma<1><<<dim3(SEQ / 128, SEQ / 128, BATCH), 256, SMEM_TOTAL>>>(
        qh, ql, kh, kl, s, nullptr, nullptr, nullptr, nullptr, nullptr, nullptr,
        scale);

    // 5) softmax -> probs hi/lo
    softmax_kernel<<<BATCH * SEQ, 256>>>(s, ph, pl);

    // 6) out = P @ V
    gemm_mma<2><<<dim3(DIM / 128, SEQ / 128, BATCH), 256, SMEM_TOTAL>>>(
        ph, pl, vth, vtl, out, nullptr, nullptr, nullptr, nullptr, nullptr, nullptr,
        1.0f);
}

// round 6
// speedup vs baseline: 4.0034x; 1.3743x over previous
#include <cuda_runtime.h>
#include <cuda_fp16.h>
#include <math.h>
#include <stdint.h>

// ---------------------------------------------------------------------------
// Problem constants
// ---------------------------------------------------------------------------
#define BATCH 8
#define SEQ   2048
#define DIM   768

// ---------------------------------------------------------------------------
// Scratch (__device__ globals; no allocation allowed)
// A-side operands: fp16 hi only. B-side operands: fp16 hi+lo (22-bit).
// ---------------------------------------------------------------------------
__device__ __half g_xh [(size_t)BATCH * SEQ * DIM];
__device__ __half g_wth[3ULL * DIM * DIM];            // W^T hi, [z][n][k]
__device__ __half g_wtl[3ULL * DIM * DIM];            // W^T lo
__device__ __half g_qh [(size_t)BATCH * SEQ * DIM];   // Q hi (A of mode1)
__device__ __half g_kh [(size_t)BATCH * SEQ * DIM];   // K hi (B of mode1)
__device__ __half g_kl [(size_t)BATCH * SEQ * DIM];   // K lo
__device__ __half g_vth[(size_t)BATCH * DIM * SEQ];   // V^T hi: [b][d][s]
__device__ __half g_vtl[(size_t)BATCH * DIM * SEQ];   // V^T lo
__device__ float  g_s  [(size_t)BATCH * SEQ * SEQ];   // fp32 logits
__device__ __half g_ph [(size_t)BATCH * SEQ * SEQ];   // probs hi (A of mode2)

// ---------------------------------------------------------------------------
// Helpers
// ---------------------------------------------------------------------------
__device__ __forceinline__ uint32_t smem_u32(const void* p) {
    uint32_t a;
    asm("{ .reg .u64 t; cvta.to.shared.u64 t, %1; cvt.u32.u64 %0, t; }"
        : "=r"(a) : "l"(p));
    return a;
}

__device__ __forceinline__ __half h_hi(float f) { return __float2half_rn(f); }
__device__ __forceinline__ __half h_lo(float f, __half h) {
    return __float2half_rn(f - __half2float(h));
}

#define LDSM4(r, addr) \
    asm volatile("ldmatrix.sync.aligned.m8n8.x4.shared.b16 {%0,%1,%2,%3}, [%4];" \
        : "=r"((r)[0]), "=r"((r)[1]), "=r"((r)[2]), "=r"((r)[3]) : "r"(addr))

#define MMA_F16(d, a, b) \
    asm volatile("mma.sync.aligned.m16n8k16.row.col.f32.f16.f16.f32 " \
        "{%0,%1,%2,%3}, {%4,%5,%6,%7}, {%8,%9}, {%0,%1,%2,%3};" \
        : "+f"((d)[0]), "+f"((d)[1]), "+f"((d)[2]), "+f"((d)[3]) \
        : "r"((a)[0]), "r"((a)[1]), "r"((a)[2]), "r"((a)[3]), \
          "r"((b)[0]), "r"((b)[1]))

#define CP_ASYNC16(dst, src) \
    asm volatile("cp.async.cg.shared.global [%0], [%1], 16;" \
        :: "r"(dst), "l"(src))
#define CP_COMMIT()  asm volatile("cp.async.commit_group;")
#define CP_WAIT1()   asm volatile("cp.async.wait_group 1;")
#define CP_WAIT0()   asm volatile("cp.async.wait_group 0;")

// ---------------------------------------------------------------------------
// GEMM tiling: BM=128, BN=128, BK=32 fp16; 8 warps (2m x 4n), warp 64x32.
// Stage = 3 tiles (A, B_hi, B_lo), each 128 rows x 32 half = 64B/row,
// XOR-swizzled (chunk ^= (row>>1)&3): conflict-free for cp.async + ldmatrix.
// 3-stage ring = 72KB/CTA -> 2 CTAs/SM (144KB, regs capped 128).
// ---------------------------------------------------------------------------
#define TILE_B  8192
#define STAGE_B (3 * TILE_B)             // 24576
#define NSTAGE  3
#define SMEM_TOTAL (NSTAGE * STAGE_B)    // 73728

__device__ __forceinline__ uint32_t sw_off(int row, int chunk) {
    return (uint32_t)(row * 64 + ((chunk ^ ((row >> 1) & 3)) << 4));
}

// MODE 0: QKV proj (K=768;  z = weight slice; -> Qh | Kh,Kl | V^Th,V^Tl)
// MODE 1: Q @ K^T  (K=768;  z = batch; -> fp32 logits * alpha)
// MODE 2: P @ V^T  (K=2048; z = batch; -> fp32 d_out)
template <int MODE>
__global__ void __launch_bounds__(256, 2)
gemm_mma(const __half* __restrict__ A,
         const __half* __restrict__ Bh, const __half* __restrict__ Bl,
         float* __restrict__ outF,
         __half* __restrict__ oQ,
         __half* __restrict__ oKh, __half* __restrict__ oKl,
         __half* __restrict__ oVh, __half* __restrict__ oVl,
         float alpha)
{
    constexpr int  K  = (MODE == 2) ? 2048 : 768;
    constexpr long sA = (MODE == 0) ? 0L
                       : (MODE == 1) ? (long)SEQ * DIM : (long)SEQ * SEQ;
    constexpr long sB = (MODE == 0) ? (long)DIM * DIM
                       : (MODE == 1) ? (long)SEQ * DIM : (long)DIM * SEQ;
    constexpr int NC  = K / 32;

    extern __shared__ char smem[];
    const uint32_t sbase = smem_u32(smem);

    const int tid  = threadIdx.x;
    const int wid  = tid >> 5;
    const int lane = tid & 31;
    const int wm   = wid & 1;      // 0..1
    const int wn   = wid >> 1;     // 0..3
    const int z    = blockIdx.z;
    const int bm   = blockIdx.y * 128;
    const int bn   = blockIdx.x * 128;

    const __half* gT[3] = { A  + (long)z * sA + (long)bm * K,
                            Bh + (long)z * sB + (long)bn * K,
                            Bl + (long)z * sB + (long)bn * K };

    // Per-thread gmem load coords: 512 16B-chunks per tile; 2 per thread.
    const int l_row0 = (tid + 0)   >> 2, l_c0 = (tid + 0)   & 3;
    const int l_row1 = (tid + 256) >> 2, l_c1 = (tid + 256) & 3;
    const uint32_t so0 = sw_off(l_row0, l_c0);
    const uint32_t so1 = sw_off(l_row1, l_c1);

    auto load_stage = [&](int slot, int k0) {
        const uint32_t soff = sbase + slot * STAGE_B;
#pragma unroll
        for (int op = 0; op < 3; op++) {
            const __half* g = gT[op];
            CP_ASYNC16(soff + op * TILE_B + so0, g + (long)l_row0 * K + k0 + l_c0 * 8);
            CP_ASYNC16(soff + op * TILE_B + so1, g + (long)l_row1 * K + k0 + l_c1 * 8);
        }
        CP_COMMIT();
    };

    // ldmatrix per-thread addressing
    const int rA = lane & 15;                          // A row within 16
    const int chA = lane >> 4;                         // 0 or 1 (16B chunk in k)
    const int rB = (lane & 7) | ((lane >> 4) << 3);    // B row within 16 (n)
    const int chB = (lane >> 3) & 1;                   // 0 or 1 (16B chunk in k)

    float acc[4][4][4];
#pragma unroll
    for (int mf = 0; mf < 4; mf++)
#pragma unroll
        for (int nf = 0; nf < 4; nf++)
#pragma unroll
            for (int q = 0; q < 4; q++) acc[mf][nf][q] = 0.0f;

    // Prologue: stages 0 and 1 in flight.
    load_stage(0, 0);
    load_stage(1, 32);

    int slot = 0;
    for (int c = 0; c < NC; c++) {
        if (c + 1 < NC) { CP_WAIT1(); } else { CP_WAIT0(); }
        // Single barrier: publishes stage c AND licenses overwriting slot c+2.
        __syncthreads();
        if (c + 2 < NC) {
            const int ns = (slot + 2 >= NSTAGE) ? slot + 2 - NSTAGE : slot + 2;
            load_stage(ns, (c + 2) * 32);
        }

        const uint32_t soff = sbase + slot * STAGE_B;
        const uint32_t aT = soff + 0 * TILE_B;
        const uint32_t bH = soff + 1 * TILE_B;
        const uint32_t bL = soff + 2 * TILE_B;

#pragma unroll
        for (int ks = 0; ks < 2; ks++) {
            uint32_t ah[4][4], bh[4][2], bl[4][2];
#pragma unroll
            for (int mf = 0; mf < 4; mf++) {
                const int row = wm * 64 + mf * 16 + rA;
                LDSM4(ah[mf], aT + sw_off(row, ks * 2 + chA));
            }
#pragma unroll
            for (int nf2 = 0; nf2 < 2; nf2++) {
                const int row = wn * 32 + nf2 * 16 + rB;
                const uint32_t ro = sw_off(row, ks * 2 + chB);
                uint32_t th[4], tl[4];
                LDSM4(th, bH + ro);
                LDSM4(tl, bL + ro);
                bh[nf2 * 2][0] = th[0]; bh[nf2 * 2][1] = th[1];
                bh[nf2 * 2 + 1][0] = th[2]; bh[nf2 * 2 + 1][1] = th[3];
                bl[nf2 * 2][0] = tl[0]; bl[nf2 * 2][1] = tl[1];
                bl[nf2 * 2 + 1][0] = tl[2]; bl[nf2 * 2 + 1][1] = tl[3];
            }
            // All hi MMAs, then all lo MMAs: same-acc RAW pairs are 16 apart.
#pragma unroll
            for (int mf = 0; mf < 4; mf++)
#pragma unroll
                for (int nf = 0; nf < 4; nf++)
                    MMA_F16(acc[mf][nf], ah[mf], bh[nf]);
#pragma unroll
            for (int mf = 0; mf < 4; mf++)
#pragma unroll
                for (int nf = 0; nf < 4; nf++)
                    MMA_F16(acc[mf][nf], ah[mf], bl[nf]);
        }

        slot = (slot + 1 >= NSTAGE) ? 0 : slot + 1;
    }

    // -----------------------------------------------------------------------
    // Epilogue: thread owns (r0, n0..n0+1) and (r0+8, n0..n0+1) per frag.
    // -----------------------------------------------------------------------
    const int gq = lane >> 2;
    const int i2 = (lane & 3) * 2;

#pragma unroll
    for (int mf = 0; mf < 4; mf++) {
#pragma unroll
        for (int nf = 0; nf < 4; nf++) {
            const int n0 = bn + wn * 32 + nf * 8 + i2;
#pragma unroll
            for (int h = 0; h < 2; h++) {
                const int mg = bm + wm * 64 + mf * 16 + gq + h * 8;
                const float f0 = acc[mf][nf][h * 2 + 0];
                const float f1 = acc[mf][nf][h * 2 + 1];

                if (MODE == 0) {
                    if (z == 0) {
                        // Q: hi only (A operand of mode1)
                        __half2 hv; hv.x = h_hi(f0); hv.y = h_hi(f1);
                        *reinterpret_cast<__half2*>(oQ + (long)mg * DIM + n0) = hv;
                    } else if (z == 1) {
                        // K: hi + lo (B operand of mode1)
                        __half h0 = h_hi(f0), h1 = h_hi(f1);
                        __half2 hv; hv.x = h0; hv.y = h1;
                        __half2 lv; lv.x = h_lo(f0, h0); lv.y = h_lo(f1, h1);
                        const long addr = (long)mg * DIM + n0;
                        *reinterpret_cast<__half2*>(oKh + addr) = hv;
                        *reinterpret_cast<__half2*>(oKl + addr) = lv;
                    } else {
                        // V: transposed hi + lo (B operand of mode2)
                        const int b = mg >> 11;
                        const int s = mg & 2047;
                        __half h0 = h_hi(f0), h1 = h_hi(f1);
                        const long a0 = ((long)b * DIM + n0) * SEQ + s;
                        const long a1 = ((long)b * DIM + n0 + 1) * SEQ + s;
                        oVh[a0] = h0; oVl[a0] = h_lo(f0, h0);
                        oVh[a1] = h1; oVl[a1] = h_lo(f1, h1);
                    }
                } else if (MODE == 1) {
                    float* dst = outF + (long)z * SEQ * SEQ + (long)mg * SEQ + n0;
                    *reinterpret_cast<float2*>(dst) =
                        make_float2(f0 * alpha, f1 * alpha);
                } else {
                    float* dst = outF + (long)z * SEQ * DIM + (long)mg * DIM + n0;
                    *reinterpret_cast<float2*>(dst) = make_float2(f0, f1);
                }
            }
        }
    }
}

// ---------------------------------------------------------------------------
// Conversion kernels
// ---------------------------------------------------------------------------
__global__ void __launch_bounds__(256)
conv_x_kernel(const float* __restrict__ x, __half* __restrict__ xh)
{
    const long i = ((long)blockIdx.x * 256 + threadIdx.x) * 4;
    float4 v = *reinterpret_cast<const float4*>(x + i);
    __half h[4];
    h[0] = h_hi(v.x); h[1] = h_hi(v.y); h[2] = h_hi(v.z); h[3] = h_hi(v.w);
    *reinterpret_cast<uint2*>(xh + i) = *reinterpret_cast<uint2*>(h);
}

// Transpose + split QKV weights: W[z][k][n] -> Wt[z][n][k] (fp16 hi/lo)
__global__ void __launch_bounds__(256)
conv_w_kernel(const float* __restrict__ W,
              __half* __restrict__ wth, __half* __restrict__ wtl)
{
    __shared__ float tile[32][33];
    const int z  = blockIdx.z;
    const int bx = blockIdx.x * 32;   // n
    const int by = blockIdx.y * 32;   // k
    const int tx = threadIdx.x & 31;
    const int ty = threadIdx.x >> 5;  // 0..7
    const float* Wz = W + (long)z * DIM * DIM;
#pragma unroll
    for (int i = 0; i < 32; i += 8)
        tile[ty + i][tx] = Wz[(long)(by + ty + i) * DIM + (bx + tx)];
    __syncthreads();
    __half* th = wth + (long)z * DIM * DIM;
    __half* tl = wtl + (long)z * DIM * DIM;
#pragma unroll
    for (int i = 0; i < 32; i += 8) {
        float f = tile[tx][ty + i];
        __half h = h_hi(f);
        const long addr = (long)(bx + ty + i) * DIM + (by + tx);
        th[addr] = h;
        tl[addr] = h_lo(f, h);
    }
}

// ---------------------------------------------------------------------------
// Softmax: fp32 logits row -> fp16 probs (hi only; A operand of mode2)
// ---------------------------------------------------------------------------
__global__ void __launch_bounds__(256)
softmax_kernel(const float* __restrict__ S, __half* __restrict__ ph)
{
    const long row = blockIdx.x;
    const float* p = S + row * (long)SEQ;
    const int t = threadIdx.x;
    __shared__ float red[8];

    float v[8];
    float m = -1e30f;
#pragma unroll
    for (int i = 0; i < 8; i++) {
        v[i] = p[t + i * 256];
        m = fmaxf(m, v[i]);
    }
#pragma unroll
    for (int o = 16; o > 0; o >>= 1)
        m = fmaxf(m, __shfl_xor_sync(0xffffffff, m, o));
    const int warp = t >> 5, lane = t & 31;
    if (lane == 0) red[warp] = m;
    __syncthreads();
    m = red[0];
#pragma unroll
    for (int w = 1; w < 8; w++) m = fmaxf(m, red[w]);
    __syncthreads();

    float s = 0.0f;
#pragma unroll
    for (int i = 0; i < 8; i++) {
        v[i] = __expf(v[i] - m);
        s += v[i];
    }
#pragma unroll
    for (int o = 16; o > 0; o >>= 1)
        s += __shfl_xor_sync(0xffffffff, s, o);
    if (lane == 0) red[warp] = s;
    __syncthreads();
    s = red[0];
#pragma unroll
    for (int w = 1; w < 8; w++) s += red[w];

    const float inv = 1.0f / s;
#pragma unroll
    for (int i = 0; i < 8; i++)
        ph[row * (long)SEQ + t + i * 256] = h_hi(v[i] * inv);
}

// ---------------------------------------------------------------------------
// Launch
// ---------------------------------------------------------------------------
extern "C" void kernel_launch(void* const* d_in, const int* in_sizes, int n_in,
                              void* d_out, int out_size)
{
    const float* x   = (const float*)d_in[0];   // [B, S, D]
    const float* QKV = (const float*)d_in[1];   // [3, D, D]
    float* out = (float*)d_out;                 // [B, S, D]

    __half *xh, *wth, *wtl, *qh, *kh, *kl, *vth, *vtl, *ph;
    float* s;
    cudaGetSymbolAddress((void**)&xh,  g_xh);
    cudaGetSymbolAddress((void**)&wth, g_wth);
    cudaGetSymbolAddress((void**)&wtl, g_wtl);
    cudaGetSymbolAddress((void**)&qh,  g_qh);
    cudaGetSymbolAddress((void**)&kh,  g_kh);
    cudaGetSymbolAddress((void**)&kl,  g_kl);
    cudaGetSymbolAddress((void**)&vth, g_vth);
    cudaGetSymbolAddress((void**)&vtl, g_vtl);
    cudaGetSymbolAddress((void**)&ph,  g_ph);
    cudaGetSymbolAddress((void**)&s,   g_s);

    cudaFuncSetAttribute(gemm_mma<0>, cudaFuncAttributeMaxDynamicSharedMemorySize, SMEM_TOTAL);
    cudaFuncSetAttribute(gemm_mma<1>, cudaFuncAttributeMaxDynamicSharedMemorySize, SMEM_TOTAL);
    cudaFuncSetAttribute(gemm_mma<2>, cudaFuncAttributeMaxDynamicSharedMemorySize, SMEM_TOTAL);

    const float scale = 1.0f / sqrtf((float)DIM);

    // 1) x -> fp16 (A operand)
    conv_x_kernel<<<(BATCH * SEQ * DIM) / 1024, 256>>>(x, xh);
    // 2) W -> W^T fp16 hi/lo (B operand)
    conv_w_kernel<<<dim3(DIM / 32, DIM / 32, 3), 256>>>(QKV, wth, wtl);

    // 3) QKV projection -> Qh | Kh,Kl | V^Th,V^Tl
    gemm_mma<0><<<dim3(DIM / 128, (BATCH * SEQ) / 128, 3), 256, SMEM_TOTAL>>>(
        xh, wth, wtl, nullptr, qh, kh, kl, vth, vtl, 1.0f);

    // 4) logits = scale * Q @ K^T
    gemm_mma<1><<<dim3(SEQ / 128, SEQ / 128, BATCH), 256, SMEM_TOTAL>>>(
        qh, kh, kl, s, nullptr, nullptr, nullptr, nullptr, nullptr, scale);

    // 5) softmax -> probs fp16
    softmax_kernel<<<BATCH * SEQ, 256>>>(s, ph);

    // 6) out = P @ V
    gemm_mma<2><<<dim3(DIM / 128, SEQ / 128, BATCH), 256, SMEM_TOTAL>>>(
        ph, vth, vtl, out, nullptr, nullptr, nullptr, nullptr, nullptr, 1.0f);
}

// round 7
// speedup vs baseline: 7.4850x; 1.8696x over previous
#include <cuda_runtime.h>
#include <cuda_fp16.h>
#include <math.h>
#include <stdint.h>

// ---------------------------------------------------------------------------
// Problem constants
// ---------------------------------------------------------------------------
#define BATCH 8
#define SEQ   2048
#define DIM   768

// ---------------------------------------------------------------------------
// Scratch (__device__ globals; no allocation allowed). All fp16 single-word.
// ---------------------------------------------------------------------------
__device__ __half g_xh [(size_t)BATCH * SEQ * DIM];
__device__ __half g_wt [3ULL * DIM * DIM];            // W^T, [z][n][k]
__device__ __half g_qh [(size_t)BATCH * SEQ * DIM];   // Q
__device__ __half g_kh [(size_t)BATCH * SEQ * DIM];   // K
__device__ __half g_vth[(size_t)BATCH * DIM * SEQ];   // V^T: [b][d][s]
__device__ __half g_s  [(size_t)BATCH * SEQ * SEQ];   // fp16 logits (scaled)
__device__ __half g_ph [(size_t)BATCH * SEQ * SEQ];   // fp16 probs

// ---------------------------------------------------------------------------
// Helpers
// ---------------------------------------------------------------------------
__device__ __forceinline__ uint32_t smem_u32(const void* p) {
    uint32_t a;
    asm("{ .reg .u64 t; cvta.to.shared.u64 t, %1; cvt.u32.u64 %0, t; }"
        : "=r"(a) : "l"(p));
    return a;
}

#define LDSM4(r, addr) \
    asm volatile("ldmatrix.sync.aligned.m8n8.x4.shared.b16 {%0,%1,%2,%3}, [%4];" \
        : "=r"((r)[0]), "=r"((r)[1]), "=r"((r)[2]), "=r"((r)[3]) : "r"(addr))

#define MMA_F16(d, a, b) \
    asm volatile("mma.sync.aligned.m16n8k16.row.col.f32.f16.f16.f32 " \
        "{%0,%1,%2,%3}, {%4,%5,%6,%7}, {%8,%9}, {%0,%1,%2,%3};" \
        : "+f"((d)[0]), "+f"((d)[1]), "+f"((d)[2]), "+f"((d)[3]) \
        : "r"((a)[0]), "r"((a)[1]), "r"((a)[2]), "r"((a)[3]), \
          "r"((b)[0]), "r"((b)[1]))

#define CP_ASYNC16(dst, src) \
    asm volatile("cp.async.cg.shared.global [%0], [%1], 16;" \
        :: "r"(dst), "l"(src))
#define CP_COMMIT()  asm volatile("cp.async.commit_group;")
#define CP_WAIT1()   asm volatile("cp.async.wait_group 1;")
#define CP_WAIT0()   asm volatile("cp.async.wait_group 0;")

// ---------------------------------------------------------------------------
// GEMM tiling: BM=128, BN=128, BK=64 fp16; 8 warps (2m x 4n), warp 64x32.
// Stage = 2 tiles (A, B), each 128 rows x 64 half = 128B/row,
// XOR-swizzled (chunk ^= row&7): conflict-free for cp.async + ldmatrix.
// 3-stage ring = 96KB/CTA -> 2 CTAs/SM (192KB, regs capped 128).
// ---------------------------------------------------------------------------
#define TILE_B  16384
#define STAGE_B (2 * TILE_B)             // 32768
#define NSTAGE  3
#define SMEM_TOTAL (NSTAGE * STAGE_B)    // 98304

__device__ __forceinline__ uint32_t sw_off(int row, int chunk) {
    return (uint32_t)(row * 128 + ((chunk ^ (row & 7)) << 4));
}

// MODE 0: QKV proj (K=768;  z = weight slice; -> Q | K | V^T)
// MODE 1: Q @ K^T  (K=768;  z = batch; -> fp16 logits * alpha)
// MODE 2: P @ V^T  (K=2048; z = batch; -> fp32 d_out)
template <int MODE>
__global__ void __launch_bounds__(256, 2)
gemm_mma(const __half* __restrict__ A, const __half* __restrict__ B,
         float* __restrict__ outF, __half* __restrict__ outH,
         __half* __restrict__ oQ, __half* __restrict__ oK,
         __half* __restrict__ oV,
         float alpha)
{
    constexpr int  K  = (MODE == 2) ? 2048 : 768;
    constexpr long sA = (MODE == 0) ? 0L
                       : (MODE == 1) ? (long)SEQ * DIM : (long)SEQ * SEQ;
    constexpr long sB = (MODE == 0) ? (long)DIM * DIM
                       : (MODE == 1) ? (long)SEQ * DIM : (long)DIM * SEQ;
    constexpr int NC  = K / 64;

    extern __shared__ char smem[];
    const uint32_t sbase = smem_u32(smem);

    const int tid  = threadIdx.x;
    const int wid  = tid >> 5;
    const int lane = tid & 31;
    const int wm   = wid & 1;      // 0..1
    const int wn   = wid >> 1;     // 0..3
    const int z    = blockIdx.z;
    const int bm   = blockIdx.y * 128;
    const int bn   = blockIdx.x * 128;

    const __half* gA = A + (long)z * sA + (long)bm * K;
    const __half* gB = B + (long)z * sB + (long)bn * K;

    // Per-thread gmem load coords: 1024 16B-chunks per tile (128 rows x 8);
    // 4 per thread.
    int l_row[4], l_c[4];
    uint32_t l_so[4];
#pragma unroll
    for (int i = 0; i < 4; i++) {
        const int idx = tid + i * 256;
        l_row[i] = idx >> 3;
        l_c[i]   = idx & 7;
        l_so[i]  = sw_off(l_row[i], l_c[i]);
    }

    auto load_stage = [&](int slot, int k0) {
        const uint32_t soff = sbase + slot * STAGE_B;
#pragma unroll
        for (int i = 0; i < 4; i++)
            CP_ASYNC16(soff + l_so[i], gA + (long)l_row[i] * K + k0 + l_c[i] * 8);
#pragma unroll
        for (int i = 0; i < 4; i++)
            CP_ASYNC16(soff + TILE_B + l_so[i],
                       gB + (long)l_row[i] * K + k0 + l_c[i] * 8);
        CP_COMMIT();
    };

    // ldmatrix per-thread addressing
    const int rA = lane & 15;                          // A row within 16
    const int chA = lane >> 4;                         // 0 or 1 (16B chunk in k)
    const int rB = (lane & 7) | ((lane >> 4) << 3);    // B row within 16 (n)
    const int chB = (lane >> 3) & 1;                   // 0 or 1 (16B chunk in k)

    float acc[4][4][4];
#pragma unroll
    for (int mf = 0; mf < 4; mf++)
#pragma unroll
        for (int nf = 0; nf < 4; nf++)
#pragma unroll
            for (int q = 0; q < 4; q++) acc[mf][nf][q] = 0.0f;

    // Prologue: stages 0 and 1 in flight.
    load_stage(0, 0);
    load_stage(1, 64);

    int slot = 0;
    for (int c = 0; c < NC; c++) {
        if (c + 1 < NC) { CP_WAIT1(); } else { CP_WAIT0(); }
        // Single barrier: publishes stage c AND licenses overwriting slot c+2.
        __syncthreads();
        if (c + 2 < NC) {
            const int ns = (slot + 2 >= NSTAGE) ? slot + 2 - NSTAGE : slot + 2;
            load_stage(ns, (c + 2) * 64);
        }

        const uint32_t aT = sbase + slot * STAGE_B;
        const uint32_t bT = aT + TILE_B;

#pragma unroll
        for (int ks = 0; ks < 4; ks++) {
            uint32_t ah[4][4], bh[4][2];
#pragma unroll
            for (int mf = 0; mf < 4; mf++) {
                const int row = wm * 64 + mf * 16 + rA;
                LDSM4(ah[mf], aT + sw_off(row, ks * 2 + chA));
            }
#pragma unroll
            for (int nf2 = 0; nf2 < 2; nf2++) {
                const int row = wn * 32 + nf2 * 16 + rB;
                uint32_t th[4];
                LDSM4(th, bT + sw_off(row, ks * 2 + chB));
                bh[nf2 * 2][0] = th[0]; bh[nf2 * 2][1] = th[1];
                bh[nf2 * 2 + 1][0] = th[2]; bh[nf2 * 2 + 1][1] = th[3];
            }
#pragma unroll
            for (int mf = 0; mf < 4; mf++)
#pragma unroll
                for (int nf = 0; nf < 4; nf++)
                    MMA_F16(acc[mf][nf], ah[mf], bh[nf]);
        }

        slot = (slot + 1 >= NSTAGE) ? 0 : slot + 1;
    }

    // -----------------------------------------------------------------------
    // Epilogue: thread owns (r0, n0..n0+1) and (r0+8, n0..n0+1) per frag.
    // -----------------------------------------------------------------------
    const int gq = lane >> 2;
    const int i2 = (lane & 3) * 2;

#pragma unroll
    for (int mf = 0; mf < 4; mf++) {
#pragma unroll
        for (int nf = 0; nf < 4; nf++) {
            const int n0 = bn + wn * 32 + nf * 8 + i2;
#pragma unroll
            for (int h = 0; h < 2; h++) {
                const int mg = bm + wm * 64 + mf * 16 + gq + h * 8;
                const float f0 = acc[mf][nf][h * 2 + 0];
                const float f1 = acc[mf][nf][h * 2 + 1];

                if (MODE == 0) {
                    if (z < 2) {
                        __half* dst = (z == 0) ? oQ : oK;
                        __half2 hv;
                        hv.x = __float2half_rn(f0);
                        hv.y = __float2half_rn(f1);
                        *reinterpret_cast<__half2*>(dst + (long)mg * DIM + n0) = hv;
                    } else {
                        // V: write transposed V^T[b][d][s]
                        const int b = mg >> 11;
                        const int s = mg & 2047;
                        oV[((long)b * DIM + n0) * SEQ + s]     = __float2half_rn(f0);
                        oV[((long)b * DIM + n0 + 1) * SEQ + s] = __float2half_rn(f1);
                    }
                } else if (MODE == 1) {
                    __half2 hv;
                    hv.x = __float2half_rn(f0 * alpha);
                    hv.y = __float2half_rn(f1 * alpha);
                    *reinterpret_cast<__half2*>(
                        outH + (long)z * SEQ * SEQ + (long)mg * SEQ + n0) = hv;
                } else {
                    float* dst = outF + (long)z * SEQ * DIM + (long)mg * DIM + n0;
                    *reinterpret_cast<float2*>(dst) = make_float2(f0, f1);
                }
            }
        }
    }
}

// ---------------------------------------------------------------------------
// Conversion kernels
// ---------------------------------------------------------------------------
__global__ void __launch_bounds__(256)
conv_x_kernel(const float* __restrict__ x, __half* __restrict__ xh)
{
    const long i = ((long)blockIdx.x * 256 + threadIdx.x) * 4;
    float4 v = *reinterpret_cast<const float4*>(x + i);
    __half h[4];
    h[0] = __float2half_rn(v.x); h[1] = __float2half_rn(v.y);
    h[2] = __float2half_rn(v.z); h[3] = __float2half_rn(v.w);
    *reinterpret_cast<uint2*>(xh + i) = *reinterpret_cast<uint2*>(h);
}

// Transpose QKV weights: W[z][k][n] -> Wt[z][n][k] (fp16)
__global__ void __launch_bounds__(256)
conv_w_kernel(const float* __restrict__ W, __half* __restrict__ wt)
{
    __shared__ float tile[32][33];
    const int z  = blockIdx.z;
    const int bx = blockIdx.x * 32;   // n
    const int by = blockIdx.y * 32;   // k
    const int tx = threadIdx.x & 31;
    const int ty = threadIdx.x >> 5;  // 0..7
    const float* Wz = W + (long)z * DIM * DIM;
#pragma unroll
    for (int i = 0; i < 32; i += 8)
        tile[ty + i][tx] = Wz[(long)(by + ty + i) * DIM + (bx + tx)];
    __syncthreads();
    __half* tz = wt + (long)z * DIM * DIM;
#pragma unroll
    for (int i = 0; i < 32; i += 8)
        tz[(long)(bx + ty + i) * DIM + (by + tx)] =
            __float2half_rn(tile[tx][ty + i]);
}

// ---------------------------------------------------------------------------
// Softmax: fp16 logits row -> fp16 probs (compute in fp32)
// ---------------------------------------------------------------------------
__global__ void __launch_bounds__(256)
softmax_kernel(const __half* __restrict__ S, __half* __restrict__ ph)
{
    const long row = blockIdx.x;
    const __half* p = S + row * (long)SEQ;
    const int t = threadIdx.x;
    __shared__ float red[8];

    float v[8];
    float m = -1e30f;
#pragma unroll
    for (int i = 0; i < 8; i++) {
        v[i] = __half2float(p[t + i * 256]);
        m = fmaxf(m, v[i]);
    }
#pragma unroll
    for (int o = 16; o > 0; o >>= 1)
        m = fmaxf(m, __shfl_xor_sync(0xffffffff, m, o));
    const int warp = t >> 5, lane = t & 31;
    if (lane == 0) red[warp] = m;
    __syncthreads();
    m = red[0];
#pragma unroll
    for (int w = 1; w < 8; w++) m = fmaxf(m, red[w]);
    __syncthreads();

    float s = 0.0f;
#pragma unroll
    for (int i = 0; i < 8; i++) {
        v[i] = __expf(v[i] - m);
        s += v[i];
    }
#pragma unroll
    for (int o = 16; o > 0; o >>= 1)
        s += __shfl_xor_sync(0xffffffff, s, o);
    if (lane == 0) red[warp] = s;
    __syncthreads();
    s = red[0];
#pragma unroll
    for (int w = 1; w < 8; w++) s += red[w];

    const float inv = 1.0f / s;
#pragma unroll
    for (int i = 0; i < 8; i++)
        ph[row * (long)SEQ + t + i * 256] = __float2half_rn(v[i] * inv);
}

// ---------------------------------------------------------------------------
// Launch
// ---------------------------------------------------------------------------
extern "C" void kernel_launch(void* const* d_in, const int* in_sizes, int n_in,
                              void* d_out, int out_size)
{
    const float* x   = (const float*)d_in[0];   // [B, S, D]
    const float* QKV = (const float*)d_in[1];   // [3, D, D]
    float* out = (float*)d_out;                 // [B, S, D]

    __half *xh, *wt, *qh, *kh, *vth, *s, *ph;
    cudaGetSymbolAddress((void**)&xh,  g_xh);
    cudaGetSymbolAddress((void**)&wt,  g_wt);
    cudaGetSymbolAddress((void**)&qh,  g_qh);
    cudaGetSymbolAddress((void**)&kh,  g_kh);
    cudaGetSymbolAddress((void**)&vth, g_vth);
    cudaGetSymbolAddress((void**)&s,   g_s);
    cudaGetSymbolAddress((void**)&ph,  g_ph);

    cudaFuncSetAttribute(gemm_mma<0>, cudaFuncAttributeMaxDynamicSharedMemorySize, SMEM_TOTAL);
    cudaFuncSetAttribute(gemm_mma<1>, cudaFuncAttributeMaxDynamicSharedMemorySize, SMEM_TOTAL);
    cudaFuncSetAttribute(gemm_mma<2>, cudaFuncAttributeMaxDynamicSharedMemorySize, SMEM_TOTAL);

    const float scale = 1.0f / sqrtf((float)DIM);

    // 1) x -> fp16
    conv_x_kernel<<<(BATCH * SEQ * DIM) / 1024, 256>>>(x, xh);
    // 2) W -> W^T fp16
    conv_w_kernel<<<dim3(DIM / 32, DIM / 32, 3), 256>>>(QKV, wt);

    // 3) QKV projection -> Q | K | V^T
    gemm_mma<0><<<dim3(DIM / 128, (BATCH * SEQ) / 128, 3), 256, SMEM_TOTAL>>>(
        xh, wt, nullptr, nullptr, qh, kh, vth, 1.0f);

    // 4) logits = scale * Q @ K^T  (fp16 out)
    gemm_mma<1><<<dim3(SEQ / 128, SEQ / 128, BATCH), 256, SMEM_TOTAL>>>(
        qh, kh, nullptr, s, nullptr, nullptr, nullptr, scale);

    // 5) softmax -> probs fp16
    softmax_kernel<<<BATCH * SEQ, 256>>>(s, ph);

    // 6) out = P @ V
    gemm_mma<2><<<dim3(DIM / 128, SEQ / 128, BATCH), 256, SMEM_TOTAL>>>(
        ph, vth, out, nullptr, nullptr, nullptr, nullptr, 1.0f);
}

// round 8
// speedup vs baseline: 7.5191x; 1.0046x over previous
#include <cuda_runtime.h>
#include <cuda_fp16.h>
#include <math.h>
#include <stdint.h>

// ---------------------------------------------------------------------------
// Problem constants
// ---------------------------------------------------------------------------
#define BATCH 8
#define SEQ   2048
#define DIM   768

// ---------------------------------------------------------------------------
// Scratch (__device__ globals; no allocation allowed). All fp16 single-word.
// ---------------------------------------------------------------------------
__device__ __half g_xh [(size_t)BATCH * SEQ * DIM];
__device__ __half g_wt [3ULL * DIM * DIM];            // W^T, [z][n][k]
__device__ __half g_qh [(size_t)BATCH * SEQ * DIM];   // Q
__device__ __half g_kh [(size_t)BATCH * SEQ * DIM];   // K
__device__ __half g_vth[(size_t)BATCH * DIM * SEQ];   // V^T: [b][d][s]
__device__ __half g_s  [(size_t)BATCH * SEQ * SEQ];   // fp16 logits (scaled)
__device__ __half g_ph [(size_t)BATCH * SEQ * SEQ];   // fp16 probs

// ---------------------------------------------------------------------------
// Helpers
// ---------------------------------------------------------------------------
__device__ __forceinline__ uint32_t smem_u32(const void* p) {
    uint32_t a;
    asm("{ .reg .u64 t; cvta.to.shared.u64 t, %1; cvt.u32.u64 %0, t; }"
        : "=r"(a) : "l"(p));
    return a;
}

#define LDSM4(r, addr) \
    asm volatile("ldmatrix.sync.aligned.m8n8.x4.shared.b16 {%0,%1,%2,%3}, [%4];" \
        : "=r"((r)[0]), "=r"((r)[1]), "=r"((r)[2]), "=r"((r)[3]) : "r"(addr))

#define MMA_F16(d, a, b) \
    asm volatile("mma.sync.aligned.m16n8k16.row.col.f32.f16.f16.f32 " \
        "{%0,%1,%2,%3}, {%4,%5,%6,%7}, {%8,%9}, {%0,%1,%2,%3};" \
        : "+f"((d)[0]), "+f"((d)[1]), "+f"((d)[2]), "+f"((d)[3]) \
        : "r"((a)[0]), "r"((a)[1]), "r"((a)[2]), "r"((a)[3]), \
          "r"((b)[0]), "r"((b)[1]))

#define CP_ASYNC16(dst, src) \
    asm volatile("cp.async.cg.shared.global [%0], [%1], 16;" \
        :: "r"(dst), "l"(src))
#define CP_COMMIT()  asm volatile("cp.async.commit_group;")
#define CP_WAIT1()   asm volatile("cp.async.wait_group 1;")
#define CP_WAIT0()   asm volatile("cp.async.wait_group 0;")

// ---------------------------------------------------------------------------
// GEMM tiling: BM=128, BN=128, BK=64 fp16; 8 warps (2m x 4n), warp 64x32.
// Stage = 2 tiles (A, B), each 128 rows x 64 half = 128B/row,
// XOR-swizzled (chunk ^= row&7): conflict-free for cp.async + ldmatrix.
// 3-stage ring = 96KB/CTA -> 2 CTAs/SM (192KB, regs capped 128).
// Fragments double-buffered: LDSM for ks+1 issued before MMAs of ks.
// ---------------------------------------------------------------------------
#define TILE_B  16384
#define STAGE_B (2 * TILE_B)             // 32768
#define NSTAGE  3
#define SMEM_TOTAL (NSTAGE * STAGE_B)    // 98304

__device__ __forceinline__ uint32_t sw_off(int row, int chunk) {
    return (uint32_t)(row * 128 + ((chunk ^ (row & 7)) << 4));
}

// MODE 0: QKV proj (K=768;  z = weight slice; -> Q | K | V^T)
// MODE 1: Q @ K^T  (K=768;  z = batch; -> fp16 logits * alpha)
// MODE 2: P @ V^T  (K=2048; z = batch; -> fp32 d_out)
template <int MODE>
__global__ void __launch_bounds__(256, 2)
gemm_mma(const __half* __restrict__ A, const __half* __restrict__ B,
         float* __restrict__ outF, __half* __restrict__ outH,
         __half* __restrict__ oQ, __half* __restrict__ oK,
         __half* __restrict__ oV,
         float alpha)
{
    constexpr int  K  = (MODE == 2) ? 2048 : 768;
    constexpr long sA = (MODE == 0) ? 0L
                       : (MODE == 1) ? (long)SEQ * DIM : (long)SEQ * SEQ;
    constexpr long sB = (MODE == 0) ? (long)DIM * DIM
                       : (MODE == 1) ? (long)SEQ * DIM : (long)DIM * SEQ;
    constexpr int NC  = K / 64;

    extern __shared__ char smem[];
    const uint32_t sbase = smem_u32(smem);

    const int tid  = threadIdx.x;
    const int wid  = tid >> 5;
    const int lane = tid & 31;
    const int wm   = wid & 1;      // 0..1
    const int wn   = wid >> 1;     // 0..3
    const int z    = blockIdx.z;
    const int bm   = blockIdx.y * 128;
    const int bn   = blockIdx.x * 128;

    const __half* gA = A + (long)z * sA + (long)bm * K;
    const __half* gB = B + (long)z * sB + (long)bn * K;

    // Per-thread gmem load coords: 1024 16B-chunks per tile (128 rows x 8);
    // 4 per thread.
    int l_row[4], l_c[4];
    uint32_t l_so[4];
#pragma unroll
    for (int i = 0; i < 4; i++) {
        const int idx = tid + i * 256;
        l_row[i] = idx >> 3;
        l_c[i]   = idx & 7;
        l_so[i]  = sw_off(l_row[i], l_c[i]);
    }

    auto load_stage = [&](int slot, int k0) {
        const uint32_t soff = sbase + slot * STAGE_B;
#pragma unroll
        for (int i = 0; i < 4; i++)
            CP_ASYNC16(soff + l_so[i], gA + (long)l_row[i] * K + k0 + l_c[i] * 8);
#pragma unroll
        for (int i = 0; i < 4; i++)
            CP_ASYNC16(soff + TILE_B + l_so[i],
                       gB + (long)l_row[i] * K + k0 + l_c[i] * 8);
        CP_COMMIT();
    };

    // ldmatrix per-thread addressing (precomputed per warp row)
    const int rA  = lane & 15;
    const int chA = lane >> 4;                         // 0/1 (16B chunk in k)
    const int rB  = (lane & 7) | ((lane >> 4) << 3);
    const int chB = (lane >> 3) & 1;

    uint32_t aRow[4], aXor[4], bRow[2], bXor[2];
#pragma unroll
    for (int mf = 0; mf < 4; mf++) {
        const int row = wm * 64 + mf * 16 + rA;
        aRow[mf] = (uint32_t)(row * 128);
        aXor[mf] = (uint32_t)(row & 7);
    }
#pragma unroll
    for (int nf2 = 0; nf2 < 2; nf2++) {
        const int row = wn * 32 + nf2 * 16 + rB;
        bRow[nf2] = (uint32_t)(row * 128);
        bXor[nf2] = (uint32_t)(row & 7);
    }

    float acc[4][4][4];
#pragma unroll
    for (int mf = 0; mf < 4; mf++)
#pragma unroll
        for (int nf = 0; nf < 4; nf++)
#pragma unroll
            for (int q = 0; q < 4; q++) acc[mf][nf][q] = 0.0f;

    // Double-buffered fragments
    uint32_t ah[2][4][4], bh[2][4][2];

    // Prologue: stages 0 and 1 in flight.
    load_stage(0, 0);
    load_stage(1, 64);

    int slot = 0;
    for (int c = 0; c < NC; c++) {
        if (c + 1 < NC) { CP_WAIT1(); } else { CP_WAIT0(); }
        // Single barrier: publishes stage c AND licenses overwriting slot c+2.
        __syncthreads();
        if (c + 2 < NC) {
            const int ns = (slot + 2 >= NSTAGE) ? slot + 2 - NSTAGE : slot + 2;
            load_stage(ns, (c + 2) * 64);
        }

        const uint32_t aT = sbase + slot * STAGE_B;
        const uint32_t bT = aT + TILE_B;

        // Fragment loader for one ks (k16 step) into buffer `buf`.
        auto ldsm_ks = [&](int buf, int ks) {
            const uint32_t c2 = (uint32_t)(ks * 2);
#pragma unroll
            for (int mf = 0; mf < 4; mf++)
                LDSM4(ah[buf][mf],
                      aT + aRow[mf] + (((c2 + chA) ^ aXor[mf]) << 4));
#pragma unroll
            for (int nf2 = 0; nf2 < 2; nf2++) {
                uint32_t th[4];
                LDSM4(th, bT + bRow[nf2] + (((c2 + chB) ^ bXor[nf2]) << 4));
                bh[buf][nf2 * 2][0]     = th[0];
                bh[buf][nf2 * 2][1]     = th[1];
                bh[buf][nf2 * 2 + 1][0] = th[2];
                bh[buf][nf2 * 2 + 1][1] = th[3];
            }
        };

        ldsm_ks(0, 0);
#pragma unroll
        for (int ks = 0; ks < 4; ks++) {
            const int cur = ks & 1;
            if (ks < 3) ldsm_ks(cur ^ 1, ks + 1);
#pragma unroll
            for (int mf = 0; mf < 4; mf++)
#pragma unroll
                for (int nf = 0; nf < 4; nf++)
                    MMA_F16(acc[mf][nf], ah[cur][mf], bh[cur][nf]);
        }

        slot = (slot + 1 >= NSTAGE) ? 0 : slot + 1;
    }

    // -----------------------------------------------------------------------
    // Epilogue: thread owns (r0, n0..n0+1) and (r0+8, n0..n0+1) per frag.
    // -----------------------------------------------------------------------
    const int gq = lane >> 2;
    const int i2 = (lane & 3) * 2;

#pragma unroll
    for (int mf = 0; mf < 4; mf++) {
#pragma unroll
        for (int nf = 0; nf < 4; nf++) {
            const int n0 = bn + wn * 32 + nf * 8 + i2;
#pragma unroll
            for (int h = 0; h < 2; h++) {
                const int mg = bm + wm * 64 + mf * 16 + gq + h * 8;
                const float f0 = acc[mf][nf][h * 2 + 0];
                const float f1 = acc[mf][nf][h * 2 + 1];

                if (MODE == 0) {
                    if (z < 2) {
                        __half* dst = (z == 0) ? oQ : oK;
                        __half2 hv = __floats2half2_rn(f0, f1);
                        *reinterpret_cast<__half2*>(dst + (long)mg * DIM + n0) = hv;
                    } else {
                        // V: write transposed V^T[b][d][s]
                        const int b = mg >> 11;
                        const int s = mg & 2047;
                        oV[((long)b * DIM + n0) * SEQ + s]     = __float2half_rn(f0);
                        oV[((long)b * DIM + n0 + 1) * SEQ + s] = __float2half_rn(f1);
                    }
                } else if (MODE == 1) {
                    __half2 hv = __floats2half2_rn(f0 * alpha, f1 * alpha);
                    *reinterpret_cast<__half2*>(
                        outH + (long)z * SEQ * SEQ + (long)mg * SEQ + n0) = hv;
                } else {
                    float* dst = outF + (long)z * SEQ * DIM + (long)mg * DIM + n0;
                    *reinterpret_cast<float2*>(dst) = make_float2(f0, f1);
                }
            }
        }
    }
}

// ---------------------------------------------------------------------------
// Conversion kernels
// ---------------------------------------------------------------------------
__global__ void __launch_bounds__(256)
conv_x_kernel(const float* __restrict__ x, __half* __restrict__ xh)
{
    const long i = ((long)blockIdx.x * 256 + threadIdx.x) * 4;
    float4 v = *reinterpret_cast<const float4*>(x + i);
    __half2 h01 = __floats2half2_rn(v.x, v.y);
    __half2 h23 = __floats2half2_rn(v.z, v.w);
    uint2 pack;
    pack.x = *reinterpret_cast<uint32_t*>(&h01);
    pack.y = *reinterpret_cast<uint32_t*>(&h23);
    *reinterpret_cast<uint2*>(xh + i) = pack;
}

// Transpose QKV weights: W[z][k][n] -> Wt[z][n][k] (fp16)
__global__ void __launch_bounds__(256)
conv_w_kernel(const float* __restrict__ W, __half* __restrict__ wt)
{
    __shared__ float tile[32][33];
    const int z  = blockIdx.z;
    const int bx = blockIdx.x * 32;   // n
    const int by = blockIdx.y * 32;   // k
    const int tx = threadIdx.x & 31;
    const int ty = threadIdx.x >> 5;  // 0..7
    const float* Wz = W + (long)z * DIM * DIM;
#pragma unroll
    for (int i = 0; i < 32; i += 8)
        tile[ty + i][tx] = Wz[(long)(by + ty + i) * DIM + (bx + tx)];
    __syncthreads();
    __half* tz = wt + (long)z * DIM * DIM;
#pragma unroll
    for (int i = 0; i < 32; i += 8)
        tz[(long)(bx + ty + i) * DIM + (by + tx)] =
            __float2half_rn(tile[tx][ty + i]);
}

// ---------------------------------------------------------------------------
// Softmax: fp16 logits row -> fp16 probs (compute in fp32)
// ---------------------------------------------------------------------------
__global__ void __launch_bounds__(256)
softmax_kernel(const __half* __restrict__ S, __half* __restrict__ ph)
{
    const long row = blockIdx.x;
    const __half* p = S + row * (long)SEQ;
    const int t = threadIdx.x;
    __shared__ float red[8];

    float v[8];
    float m = -1e30f;
#pragma unroll
    for (int i = 0; i < 8; i++) {
        v[i] = __half2float(p[t + i * 256]);
        m = fmaxf(m, v[i]);
    }
#pragma unroll
    for (int o = 16; o > 0; o >>= 1)
        m = fmaxf(m, __shfl_xor_sync(0xffffffff, m, o));
    const int warp = t >> 5, lane = t & 31;
    if (lane == 0) red[warp] = m;
    __syncthreads();
    m = red[0];
#pragma unroll
    for (int w = 1; w < 8; w++) m = fmaxf(m, red[w]);
    __syncthreads();

    float s = 0.0f;
#pragma unroll
    for (int i = 0; i < 8; i++) {
        v[i] = __expf(v[i] - m);
        s += v[i];
    }
#pragma unroll
    for (int o = 16; o > 0; o >>= 1)
        s += __shfl_xor_sync(0xffffffff, s, o);
    if (lane == 0) red[warp] = s;
    __syncthreads();
    s = red[0];
#pragma unroll
    for (int w = 1; w < 8; w++) s += red[w];

    const float inv = 1.0f / s;
#pragma unroll
    for (int i = 0; i < 8; i++)
        ph[row * (long)SEQ + t + i * 256] = __float2half_rn(v[i] * inv);
}

// ---------------------------------------------------------------------------
// Launch
// ---------------------------------------------------------------------------
extern "C" void kernel_launch(void* const* d_in, const int* in_sizes, int n_in,
                              void* d_out, int out_size)
{
    const float* x   = (const float*)d_in[0];   // [B, S, D]
    const float* QKV = (const float*)d_in[1];   // [3, D, D]
    float* out = (float*)d_out;                 // [B, S, D]

    __half *xh, *wt, *qh, *kh, *vth, *s, *ph;
    cudaGetSymbolAddress((void**)&xh,  g_xh);
    cudaGetSymbolAddress((void**)&wt,  g_wt);
    cudaGetSymbolAddress((void**)&qh,  g_qh);
    cudaGetSymbolAddress((void**)&kh,  g_kh);
    cudaGetSymbolAddress((void**)&vth, g_vth);
    cudaGetSymbolAddress((void**)&s,   g_s);
    cudaGetSymbolAddress((void**)&ph,  g_ph);

    cudaFuncSetAttribute(gemm_mma<0>, cudaFuncAttributeMaxDynamicSharedMemorySize, SMEM_TOTAL);
    cudaFuncSetAttribute(gemm_mma<1>, cudaFuncAttributeMaxDynamicSharedMemorySize, SMEM_TOTAL);
    cudaFuncSetAttribute(gemm_mma<2>, cudaFuncAttributeMaxDynamicSharedMemorySize, SMEM_TOTAL);

    const float scale = 1.0f / sqrtf((float)DIM);

    // 1) x -> fp16
    conv_x_kernel<<<(BATCH * SEQ * DIM) / 1024, 256>>>(x, xh);
    // 2) W -> W^T fp16
    conv_w_kernel<<<dim3(DIM / 32, DIM / 32, 3), 256>>>(QKV, wt);

    // 3) QKV projection -> Q | K | V^T
    gemm_mma<0><<<dim3(DIM / 128, (BATCH * SEQ) / 128, 3), 256, SMEM_TOTAL>>>(
        xh, wt, nullptr, nullptr, qh, kh, vth, 1.0f);

    // 4) logits = scale * Q @ K^T  (fp16 out)
    gemm_mma<1><<<dim3(SEQ / 128, SEQ / 128, BATCH), 256, SMEM_TOTAL>>>(
        qh, kh, nullptr, s, nullptr, nullptr, nullptr, scale);

    // 5) softmax -> probs fp16
    softmax_kernel<<<BATCH * SEQ, 256>>>(s, ph);

    // 6) out = P @ V
    gemm_mma<2><<<dim3(DIM / 128, SEQ / 128, BATCH), 256, SMEM_TOTAL>>>(
        ph, vth, out, nullptr, nullptr, nullptr, nullptr, 1.0f);
}